// round 7
// baseline (speedup 1.0000x reference)
#include <cuda_runtime.h>
#include <cuda_bf16.h>
#include <cstdint>
#include <math.h>

#define S 4096
#define D 1024
#define H 16
#define HD 64
typedef __nv_bfloat16 bf16;

// ---------------- device scratch -------------------------------------------
__device__ bf16 g_Xhi[(size_t)S * D], g_Xlo[(size_t)S * D];
__device__ bf16 g_Whi[4 * (size_t)D * D], g_Wlo[4 * (size_t)D * D];
__device__ bf16 g_Qhi[(size_t)S * D], g_Qlo[(size_t)S * D];
__device__ bf16 g_Khi[(size_t)S * D], g_Klo[(size_t)S * D];
__device__ bf16 g_Vhi[(size_t)S * D], g_Vlo[(size_t)S * D];
__device__ bf16 g_Ohi[(size_t)S * D], g_Olo[(size_t)S * D];
__device__ float g_cos[S * 32], g_sin[S * 32];

// ---------------- helpers ---------------------------------------------------
__device__ __forceinline__ uint32_t smem_u32(const void* p) {
    uint32_t a;
    asm("{ .reg .u64 t; cvta.to.shared.u64 t, %1; cvt.u32.u64 %0, t; }"
        : "=r"(a) : "l"(p));
    return a;
}

__device__ __forceinline__ void cp16(uint32_t saddr, const void* g) {
    asm volatile("cp.async.cg.shared.global [%0], [%1], 16;" :: "r"(saddr), "l"(g));
}

__device__ __forceinline__ void ldsm4(uint32_t a, uint32_t r[4]) {
    asm volatile("ldmatrix.sync.aligned.m8n8.x4.shared.b16 {%0,%1,%2,%3}, [%4];"
                 : "=r"(r[0]), "=r"(r[1]), "=r"(r[2]), "=r"(r[3]) : "r"(a));
}

__device__ __forceinline__ void ldsm4t(uint32_t a, uint32_t r[4]) {
    asm volatile("ldmatrix.sync.aligned.m8n8.x4.trans.shared.b16 {%0,%1,%2,%3}, [%4];"
                 : "=r"(r[0]), "=r"(r[1]), "=r"(r[2]), "=r"(r[3]) : "r"(a));
}

// NOT volatile: register-only op; lets ptxas schedule around RAW chains.
__device__ __forceinline__ void mma16816(float c[4], const uint32_t a[4],
                                         uint32_t b0, uint32_t b1) {
    asm("mma.sync.aligned.m16n8k16.row.col.f32.bf16.bf16.f32 "
        "{%0,%1,%2,%3}, {%4,%5,%6,%7}, {%8,%9}, {%0,%1,%2,%3};"
        : "+f"(c[0]), "+f"(c[1]), "+f"(c[2]), "+f"(c[3])
        : "r"(a[0]), "r"(a[1]), "r"(a[2]), "r"(a[3]), "r"(b0), "r"(b1));
}

__device__ __forceinline__ uint32_t pack_bf2(float a, float b) {
    bf16 ha = __float2bfloat16(a), hb = __float2bfloat16(b);
    return ((uint32_t)__bfloat16_as_ushort(hb) << 16) | __bfloat16_as_ushort(ha);
}

// ---------------- split / rope-table kernels --------------------------------
__device__ __forceinline__ void split_one(const float* src, bf16* hi, bf16* lo, size_t i) {
    float x = src[i];
    bf16 h = __float2bfloat16(x);
    hi[i] = h;
    lo[i] = __float2bfloat16(x - __bfloat162float(h));
}

__global__ void split_x_kernel(const float* __restrict__ x) {
    size_t i = (size_t)blockIdx.x * 256 + threadIdx.x;
    split_one(x, g_Xhi, g_Xlo, i);
}

__global__ void split_w_kernel(const float* __restrict__ Wq, const float* __restrict__ Wk,
                               const float* __restrict__ Wv, const float* __restrict__ Wo) {
    int z = blockIdx.z;
    const float* W = (z == 0) ? Wq : (z == 1) ? Wk : (z == 2) ? Wv : Wo;
    size_t i = (size_t)blockIdx.x * 256 + threadIdx.x;
    split_one(W, g_Whi + (size_t)z * D * D, g_Wlo + (size_t)z * D * D, i);
}

__global__ void rope_table_kernel(const int* __restrict__ pos) {
    int m = blockIdx.x;
    int i = threadIdx.x;  // pair index 0..31
    double f = pow(10000.0, -(double)(2 * i) / 64.0);
    float ang = (float)pos[m] * (float)f;
    float sv, cv;
    sincosf(ang, &sv, &cv);
    g_cos[m * 32 + i] = cv;
    g_sin[m * 32 + i] = sv;
}

// ---------------- split-bf16 HMMA GEMM:  Y = A @ B^T -------------------------
// CTA 128x128, 4 warps (2x2), each warp 64x64 output. k-chunk 32, 2 stages.
#define MM_SP    80                 // padded row bytes (32 bf16 + 16B pad)
#define MM_MAT   (128 * MM_SP)      // 10240 B
#define MM_STAGE (4 * MM_MAT)       // Ah, Al, Bh, Bl
#define MM_SMEM  (2 * MM_STAGE)     // 81920 B

__device__ __forceinline__ void mm_load_stage(uint32_t sb, int st, int c,
                                              const bf16* A_h, const bf16* A_l,
                                              const bf16* B_h, const bf16* B_l) {
    const bf16* srcs[4] = {A_h, A_l, B_h, B_l};
    int t = threadIdx.x;
#pragma unroll
    for (int i = 0; i < 16; i++) {
        int cid = t + i * 128;                 // 0..2047
        int mi = cid >> 9;                     // matrix 0..3
        int r  = (cid >> 2) & 127;             // row 0..127
        int q  = cid & 3;                      // 16B chunk 0..3
        const bf16* g = srcs[mi] + (size_t)r * D + c * 32 + q * 8;
        cp16(sb + st * MM_STAGE + mi * MM_MAT + r * MM_SP + q * 16, g);
    }
}

__device__ __forceinline__ void mm_stage_compute(uint32_t so, int wm, int wn,
                                                 int lane, float acc[4][8][4]) {
    const int lr = lane & 15, lc = lane >> 4;
#pragma unroll
    for (int ks = 0; ks < 2; ks++) {
        uint32_t a4[4][4], bh[8][2], bl[8][2], t4[4];
#pragma unroll
        for (int i = 0; i < 4; i++)
            ldsm4(so + 0 * MM_MAT + (wm * 64 + i * 16 + lr) * MM_SP + ks * 32 + lc * 16, a4[i]);
#pragma unroll
        for (int jj = 0; jj < 4; jj++) {
            ldsm4(so + 2 * MM_MAT + (wn * 64 + jj * 16 + lr) * MM_SP + ks * 32 + lc * 16, t4);
            bh[2 * jj][0] = t4[0]; bh[2 * jj][1] = t4[2];
            bh[2 * jj + 1][0] = t4[1]; bh[2 * jj + 1][1] = t4[3];
        }
        // pass 1: Ah*Bh — 32 independent MMAs
#pragma unroll
        for (int i = 0; i < 4; i++)
#pragma unroll
            for (int j = 0; j < 8; j++)
                mma16816(acc[i][j], a4[i], bh[j][0], bh[j][1]);
#pragma unroll
        for (int jj = 0; jj < 4; jj++) {
            ldsm4(so + 3 * MM_MAT + (wn * 64 + jj * 16 + lr) * MM_SP + ks * 32 + lc * 16, t4);
            bl[2 * jj][0] = t4[0]; bl[2 * jj][1] = t4[2];
            bl[2 * jj + 1][0] = t4[1]; bl[2 * jj + 1][1] = t4[3];
        }
        // pass 2: Ah*Bl — dependent on pass 1, 32 MMAs apart
#pragma unroll
        for (int i = 0; i < 4; i++)
#pragma unroll
            for (int j = 0; j < 8; j++)
                mma16816(acc[i][j], a4[i], bl[j][0], bl[j][1]);
#pragma unroll
        for (int i = 0; i < 4; i++)
            ldsm4(so + 1 * MM_MAT + (wm * 64 + i * 16 + lr) * MM_SP + ks * 32 + lc * 16, a4[i]);
        // pass 3: Al*Bh — dependent on pass 2, 32 MMAs apart
#pragma unroll
        for (int i = 0; i < 4; i++)
#pragma unroll
            for (int j = 0; j < 8; j++)
                mma16816(acc[i][j], a4[i], bh[j][0], bh[j][1]);
    }
}

// mode 0: rope + bf16 hi/lo out; mode 1: bf16 hi/lo out; mode 2: fp32 out.
__device__ void mm_body(const bf16* Ah, const bf16* Al, const bf16* Bh, const bf16* Bl,
                        int mode, float* outF, bf16* outH, bf16* outL) {
    extern __shared__ char smem[];
    uint32_t sb = smem_u32(smem);
    const int tid = threadIdx.x, lane = tid & 31, wid = tid >> 5;   // wid 0..3
    const int wm = wid >> 1, wn = wid & 1;
    const int m0 = blockIdx.y * 128, n0 = blockIdx.x * 128;

    const bf16* A_h = Ah + (size_t)m0 * D;
    const bf16* A_l = Al + (size_t)m0 * D;
    const bf16* B_h = Bh + (size_t)n0 * D;
    const bf16* B_l = Bl + (size_t)n0 * D;

    float acc[4][8][4];
#pragma unroll
    for (int i = 0; i < 4; i++)
#pragma unroll
        for (int j = 0; j < 8; j++)
#pragma unroll
            for (int e = 0; e < 4; e++) acc[i][j][e] = 0.0f;

    mm_load_stage(sb, 0, 0, A_h, A_l, B_h, B_l);
    asm volatile("cp.async.commit_group;" ::: "memory");

#pragma unroll 1
    for (int c = 0; c < 32; c++) {
        int st = c & 1;
        if (c + 1 < 32) {
            mm_load_stage(sb, st ^ 1, c + 1, A_h, A_l, B_h, B_l);
            asm volatile("cp.async.commit_group;" ::: "memory");
            asm volatile("cp.async.wait_group 1;" ::: "memory");
        } else {
            asm volatile("cp.async.wait_group 0;" ::: "memory");
        }
        __syncthreads();
        mm_stage_compute(sb + st * MM_STAGE, wm, wn, lane, acc);
        __syncthreads();
    }

    const int g = lane >> 2, tig = lane & 3;
#pragma unroll
    for (int i = 0; i < 4; i++)
#pragma unroll
        for (int j = 0; j < 8; j++) {
            const int m = m0 + wm * 64 + i * 16 + g;
            const int n = n0 + wn * 64 + j * 8 + tig * 2;
#pragma unroll
            for (int rr = 0; rr < 2; rr++) {
                const int mm = m + rr * 8;
                float e = acc[i][j][rr * 2], o = acc[i][j][rr * 2 + 1];
                if (mode == 0) {
                    const int pidx = (n & 63) >> 1;
                    const float cv = g_cos[mm * 32 + pidx];
                    const float sv = g_sin[mm * 32 + pidx];
                    const float e2 = e * cv - o * sv;
                    const float o2 = e * sv + o * cv;
                    e = e2; o = o2;
                }
                if (mode == 2) {
                    *(float2*)(outF + (size_t)mm * D + n) = make_float2(e, o);
                } else {
                    bf16 he = __float2bfloat16(e), ho = __float2bfloat16(o);
                    float le = e - __bfloat162float(he);
                    float lo_ = o - __bfloat162float(ho);
                    *(uint32_t*)(outH + (size_t)mm * D + n) =
                        ((uint32_t)__bfloat16_as_ushort(ho) << 16) | __bfloat16_as_ushort(he);
                    *(uint32_t*)(outL + (size_t)mm * D + n) = pack_bf2(le, lo_);
                }
            }
        }
}

__global__ __launch_bounds__(128, 2) void mm_qkv_kernel() {
    const int z = blockIdx.z;
    const bf16* Bh = g_Whi + (size_t)z * D * D;
    const bf16* Bl = g_Wlo + (size_t)z * D * D;
    bf16* oh = (z == 0) ? g_Qhi : (z == 1) ? g_Khi : g_Vhi;
    bf16* ol = (z == 0) ? g_Qlo : (z == 1) ? g_Klo : g_Vlo;
    mm_body(g_Xhi, g_Xlo, Bh, Bl, (z < 2) ? 0 : 1, (float*)0, oh, ol);
}

__global__ __launch_bounds__(128, 2) void mm_out_kernel(float* __restrict__ out) {
    mm_body(g_Ohi, g_Olo, g_Whi + 3ull * D * D, g_Wlo + 3ull * D * D, 2, out, (bf16*)0, (bf16*)0);
}

// ---------------- HMMA flash attention --------------------------------------
// CTA = 64 q rows x 1 head, 4 warps (each m16). kv tiles of 64, single buffer.
#define AT_SP   144                 // padded row bytes (64 bf16 = 128B + 16B pad)
#define AT_MAT  (64 * AT_SP)        // 9216 B
#define AT_SMEM (6 * AT_MAT)        // Qh Ql Kh Kl Vh Vl = 55296 B

__device__ __forceinline__ void at_load64(uint32_t sdst, const bf16* g) {
    int t = threadIdx.x;
#pragma unroll
    for (int i = 0; i < 4; i++) {
        int cid = t + i * 128;         // 0..511
        int r = cid >> 3;              // row 0..63
        int q = cid & 7;               // 16B chunk 0..7 (128B per row)
        cp16(sdst + r * AT_SP + q * 16, g + (size_t)r * D + q * 8);
    }
}

__global__ __launch_bounds__(128) void attn_kernel() {
    extern __shared__ char smem[];
    uint32_t sb = smem_u32(smem);
    const int tid = threadIdx.x, lane = tid & 31, w = tid >> 5;
    const int qt = (int)gridDim.x - 1 - (int)blockIdx.x;   // heavy first
    const int h = blockIdx.y;
    const int qbase = qt * 64;
    const int lr = lane & 15, lc = lane >> 4;
    const int g = lane >> 2, tig = lane & 3;

    at_load64(sb + 0 * AT_MAT, g_Qhi + (size_t)qbase * D + h * HD);
    at_load64(sb + 1 * AT_MAT, g_Qlo + (size_t)qbase * D + h * HD);
    asm volatile("cp.async.commit_group;" ::: "memory");
    asm volatile("cp.async.wait_group 0;" ::: "memory");
    __syncthreads();

    uint32_t qh[4][4], ql[4][4];
#pragma unroll
    for (int ks = 0; ks < 4; ks++) {
        ldsm4(sb + 0 * AT_MAT + (w * 16 + lr) * AT_SP + ks * 32 + lc * 16, qh[ks]);
        ldsm4(sb + 1 * AT_MAT + (w * 16 + lr) * AT_SP + ks * 32 + lc * 16, ql[ks]);
    }

    float o[8][4];
#pragma unroll
    for (int j = 0; j < 8; j++)
#pragma unroll
        for (int e = 0; e < 4; e++) o[j][e] = 0.0f;
    float m0r = -1e30f, m1r = -1e30f, l0 = 0.0f, l1 = 0.0f;

#pragma unroll 1
    for (int kt = 0; kt <= qt; kt++) {
        const size_t koff = (size_t)(kt * 64) * D + h * HD;
        __syncthreads();   // all warps done reading smem from previous tile
        at_load64(sb + 2 * AT_MAT, g_Khi + koff);
        at_load64(sb + 3 * AT_MAT, g_Klo + koff);
        at_load64(sb + 4 * AT_MAT, g_Vhi + koff);
        at_load64(sb + 5 * AT_MAT, g_Vlo + koff);
        asm volatile("cp.async.commit_group;" ::: "memory");
        asm volatile("cp.async.wait_group 0;" ::: "memory");
        __syncthreads();

        float s[8][4];
#pragma unroll
        for (int j = 0; j < 8; j++)
#pragma unroll
            for (int e = 0; e < 4; e++) s[j][e] = 0.0f;

        // --- S = (Qh+Ql)(Kh+Kl)^T, 3 passes of 8 independent MMAs each ---
#pragma unroll
        for (int ks = 0; ks < 4; ks++) {
            uint32_t kh[4][4];
#pragma unroll
            for (int jj = 0; jj < 4; jj++)
                ldsm4(sb + 2 * AT_MAT + (jj * 16 + lr) * AT_SP + ks * 32 + lc * 16, kh[jj]);
#pragma unroll
            for (int jj = 0; jj < 4; jj++) {
                mma16816(s[2 * jj],     qh[ks], kh[jj][0], kh[jj][2]);
                mma16816(s[2 * jj + 1], qh[ks], kh[jj][1], kh[jj][3]);
            }
#pragma unroll
            for (int jj = 0; jj < 4; jj++) {
                mma16816(s[2 * jj],     ql[ks], kh[jj][0], kh[jj][2]);
                mma16816(s[2 * jj + 1], ql[ks], kh[jj][1], kh[jj][3]);
            }
            uint32_t kl[4][4];
#pragma unroll
            for (int jj = 0; jj < 4; jj++)
                ldsm4(sb + 3 * AT_MAT + (jj * 16 + lr) * AT_SP + ks * 32 + lc * 16, kl[jj]);
#pragma unroll
            for (int jj = 0; jj < 4; jj++) {
                mma16816(s[2 * jj],     qh[ks], kl[jj][0], kl[jj][2]);
                mma16816(s[2 * jj + 1], qh[ks], kl[jj][1], kl[jj][3]);
            }
        }

        // --- scale + causal mask (diag tile only) ---
        const bool diag = (kt == qt);
#pragma unroll
        for (int j = 0; j < 8; j++)
#pragma unroll
            for (int e = 0; e < 4; e++) {
                float v = s[j][e] * 0.125f;
                if (diag) {
                    const int kvc = kt * 64 + j * 8 + tig * 2 + (e & 1);
                    const int qr  = qbase + w * 16 + g + ((e >> 1) << 3);
                    if (kvc > qr) v = -1e30f;
                }
                s[j][e] = v;
            }

        // --- online softmax ---
        float mx0 = -1e30f, mx1 = -1e30f;
#pragma unroll
        for (int j = 0; j < 8; j++) {
            mx0 = fmaxf(mx0, fmaxf(s[j][0], s[j][1]));
            mx1 = fmaxf(mx1, fmaxf(s[j][2], s[j][3]));
        }
        mx0 = fmaxf(mx0, __shfl_xor_sync(0xffffffffu, mx0, 1));
        mx0 = fmaxf(mx0, __shfl_xor_sync(0xffffffffu, mx0, 2));
        mx1 = fmaxf(mx1, __shfl_xor_sync(0xffffffffu, mx1, 1));
        mx1 = fmaxf(mx1, __shfl_xor_sync(0xffffffffu, mx1, 2));
        const float nm0 = fmaxf(m0r, mx0), nm1 = fmaxf(m1r, mx1);
        const float sc0 = __expf(m0r - nm0), sc1 = __expf(m1r - nm1);
        m0r = nm0; m1r = nm1;
        l0 *= sc0; l1 *= sc1;
#pragma unroll
        for (int j = 0; j < 8; j++) {
            o[j][0] *= sc0; o[j][1] *= sc0;
            o[j][2] *= sc1; o[j][3] *= sc1;
        }
#pragma unroll
        for (int j = 0; j < 8; j++) {
            s[j][0] = __expf(s[j][0] - nm0); s[j][1] = __expf(s[j][1] - nm0);
            s[j][2] = __expf(s[j][2] - nm1); s[j][3] = __expf(s[j][3] - nm1);
            l0 += s[j][0] + s[j][1];
            l1 += s[j][2] + s[j][3];
        }

        // --- O += (Ph+Pl)(Vh+Vl), 3 passes of 8 independent MMAs ---
#pragma unroll
        for (int ks = 0; ks < 4; ks++) {
            uint32_t pa[4], pl[4];
            {
                float r0, r1, r2, r3, r4, r5, r6, r7;
                bf16 b;
                b = __float2bfloat16(s[2 * ks][0]); r0 = s[2 * ks][0] - __bfloat162float(b);
                bf16 b1v = __float2bfloat16(s[2 * ks][1]); r1 = s[2 * ks][1] - __bfloat162float(b1v);
                pa[0] = ((uint32_t)__bfloat16_as_ushort(b1v) << 16) | __bfloat16_as_ushort(b);
                b = __float2bfloat16(s[2 * ks][2]); r2 = s[2 * ks][2] - __bfloat162float(b);
                b1v = __float2bfloat16(s[2 * ks][3]); r3 = s[2 * ks][3] - __bfloat162float(b1v);
                pa[1] = ((uint32_t)__bfloat16_as_ushort(b1v) << 16) | __bfloat16_as_ushort(b);
                b = __float2bfloat16(s[2 * ks + 1][0]); r4 = s[2 * ks + 1][0] - __bfloat162float(b);
                b1v = __float2bfloat16(s[2 * ks + 1][1]); r5 = s[2 * ks + 1][1] - __bfloat162float(b1v);
                pa[2] = ((uint32_t)__bfloat16_as_ushort(b1v) << 16) | __bfloat16_as_ushort(b);
                b = __float2bfloat16(s[2 * ks + 1][2]); r6 = s[2 * ks + 1][2] - __bfloat162float(b);
                b1v = __float2bfloat16(s[2 * ks + 1][3]); r7 = s[2 * ks + 1][3] - __bfloat162float(b1v);
                pa[3] = ((uint32_t)__bfloat16_as_ushort(b1v) << 16) | __bfloat16_as_ushort(b);
                pl[0] = pack_bf2(r0, r1); pl[1] = pack_bf2(r2, r3);
                pl[2] = pack_bf2(r4, r5); pl[3] = pack_bf2(r6, r7);
            }
            uint32_t vh[4][4];
#pragma unroll
            for (int jj = 0; jj < 4; jj++)
                ldsm4t(sb + 4 * AT_MAT + (ks * 16 + lr) * AT_SP + jj * 32 + lc * 16, vh[jj]);
#pragma unroll
            for (int jj = 0; jj < 4; jj++) {
                mma16816(o[2 * jj],     pa, vh[jj][0], vh[jj][1]);
                mma16816(o[2 * jj + 1], pa, vh[jj][2], vh[jj][3]);
            }
#pragma unroll
            for (int jj = 0; jj < 4; jj++) {
                mma16816(o[2 * jj],     pl, vh[jj][0], vh[jj][1]);
                mma16816(o[2 * jj + 1], pl, vh[jj][2], vh[jj][3]);
            }
            uint32_t vl[4][4];
#pragma unroll
            for (int jj = 0; jj < 4; jj++)
                ldsm4t(sb + 5 * AT_MAT + (ks * 16 + lr) * AT_SP + jj * 32 + lc * 16, vl[jj]);
#pragma unroll
            for (int jj = 0; jj < 4; jj++) {
                mma16816(o[2 * jj],     pa, vl[jj][0], vl[jj][1]);
                mma16816(o[2 * jj + 1], pa, vl[jj][2], vl[jj][3]);
            }
        }
    }

    // --- finalize ---
    l0 += __shfl_xor_sync(0xffffffffu, l0, 1);
    l0 += __shfl_xor_sync(0xffffffffu, l0, 2);
    l1 += __shfl_xor_sync(0xffffffffu, l1, 1);
    l1 += __shfl_xor_sync(0xffffffffu, l1, 2);
    const float i0 = 1.0f / l0, i1 = 1.0f / l1;

#pragma unroll
    for (int j = 0; j < 8; j++) {
        const int n = h * HD + j * 8 + tig * 2;
#pragma unroll
        for (int rr = 0; rr < 2; rr++) {
            const int mm = qbase + w * 16 + g + rr * 8;
            const float inv = rr ? i1 : i0;
            const float e = o[j][2 * rr] * inv;
            const float od = o[j][2 * rr + 1] * inv;
            bf16 he = __float2bfloat16(e), ho = __float2bfloat16(od);
            float le = e - __bfloat162float(he);
            float lo_ = od - __bfloat162float(ho);
            *(uint32_t*)(g_Ohi + (size_t)mm * D + n) =
                ((uint32_t)__bfloat16_as_ushort(ho) << 16) | __bfloat16_as_ushort(he);
            *(uint32_t*)(g_Olo + (size_t)mm * D + n) = pack_bf2(le, lo_);
        }
    }
}

// ---------------------------------------------------------------------------
extern "C" void kernel_launch(void* const* d_in, const int* in_sizes, int n_in,
                              void* d_out, int out_size) {
    (void)in_sizes; (void)n_in; (void)out_size;
    const float* x   = (const float*)d_in[0];
    const int*   pos = (const int*)  d_in[1];
    const float* Wq  = (const float*)d_in[2];
    const float* Wk  = (const float*)d_in[3];
    const float* Wv  = (const float*)d_in[4];
    const float* Wo  = (const float*)d_in[5];
    float* out = (float*)d_out;

    cudaFuncSetAttribute(mm_qkv_kernel, cudaFuncAttributeMaxDynamicSharedMemorySize, MM_SMEM);
    cudaFuncSetAttribute(mm_out_kernel, cudaFuncAttributeMaxDynamicSharedMemorySize, MM_SMEM);
    cudaFuncSetAttribute(attn_kernel, cudaFuncAttributeMaxDynamicSharedMemorySize, AT_SMEM);

    split_x_kernel<<<(S * D) / 256, 256>>>(x);
    split_w_kernel<<<dim3((D * D) / 256, 1, 4), 256>>>(Wq, Wk, Wv, Wo);
    rope_table_kernel<<<S, 32>>>(pos);

    mm_qkv_kernel<<<dim3(D / 128, S / 128, 3), 128, MM_SMEM>>>();
    attn_kernel<<<dim3(S / 64, H), 128, AT_SMEM>>>();
    mm_out_kernel<<<dim3(D / 128, S / 128, 1), 128, MM_SMEM>>>(out);
}

// round 8
// speedup vs baseline: 1.0839x; 1.0839x over previous
#include <cuda_runtime.h>
#include <cuda_fp16.h>
#include <cstdint>
#include <math.h>

#define S 4096
#define D 1024
#define H 16
#define HD 64
#define LO_SCALE 2048.0f
#define INV_LO (1.0f / 2048.0f)

// ---------------- device scratch -------------------------------------------
__device__ __half g_Xhi[(size_t)S * D], g_Xlo[(size_t)S * D];
__device__ __half g_Whi[4 * (size_t)D * D], g_Wlo[4 * (size_t)D * D];
__device__ __half g_Qhi[(size_t)S * D], g_Qlo[(size_t)S * D];
__device__ __half g_Khi[(size_t)S * D], g_Klo[(size_t)S * D];
__device__ __half g_Vhi[(size_t)S * D], g_Vlo[(size_t)S * D];
__device__ __half g_Ohi[(size_t)S * D], g_Olo[(size_t)S * D];
__device__ float g_cos[S * 32], g_sin[S * 32];

// ---------------- helpers ---------------------------------------------------
__device__ __forceinline__ uint32_t smem_u32(const void* p) {
    uint32_t a;
    asm("{ .reg .u64 t; cvta.to.shared.u64 t, %1; cvt.u32.u64 %0, t; }"
        : "=r"(a) : "l"(p));
    return a;
}

__device__ __forceinline__ void cp16(uint32_t saddr, const void* g) {
    asm volatile("cp.async.cg.shared.global [%0], [%1], 16;" :: "r"(saddr), "l"(g));
}

__device__ __forceinline__ void ldsm4(uint32_t a, uint32_t r[4]) {
    asm volatile("ldmatrix.sync.aligned.m8n8.x4.shared.b16 {%0,%1,%2,%3}, [%4];"
                 : "=r"(r[0]), "=r"(r[1]), "=r"(r[2]), "=r"(r[3]) : "r"(a));
}

__device__ __forceinline__ void ldsm4t(uint32_t a, uint32_t r[4]) {
    asm volatile("ldmatrix.sync.aligned.m8n8.x4.trans.shared.b16 {%0,%1,%2,%3}, [%4];"
                 : "=r"(r[0]), "=r"(r[1]), "=r"(r[2]), "=r"(r[3]) : "r"(a));
}

// f32-accumulate fp16 MMA
__device__ __forceinline__ void mma16816(float c[4], const uint32_t a[4],
                                         uint32_t b0, uint32_t b1) {
    asm("mma.sync.aligned.m16n8k16.row.col.f32.f16.f16.f32 "
        "{%0,%1,%2,%3}, {%4,%5,%6,%7}, {%8,%9}, {%0,%1,%2,%3};"
        : "+f"(c[0]), "+f"(c[1]), "+f"(c[2]), "+f"(c[3])
        : "r"(a[0]), "r"(a[1]), "r"(a[2]), "r"(a[3]), "r"(b0), "r"(b1));
}

// f16-accumulate fp16 MMA (correction path)
__device__ __forceinline__ void mma16816h(uint32_t c[2], const uint32_t a[4],
                                          uint32_t b0, uint32_t b1) {
    asm("mma.sync.aligned.m16n8k16.row.col.f16.f16.f16.f16 "
        "{%0,%1}, {%2,%3,%4,%5}, {%6,%7}, {%0,%1};"
        : "+r"(c[0]), "+r"(c[1])
        : "r"(a[0]), "r"(a[1]), "r"(a[2]), "r"(a[3]), "r"(b0), "r"(b1));
}

__device__ __forceinline__ uint32_t pack_h2(float a, float b) {
    __half2 h = __floats2half2_rn(a, b);
    return *(uint32_t*)&h;
}

// ---------------- split / rope-table kernels --------------------------------
__device__ __forceinline__ void split_one(const float* src, __half* hi, __half* lo, size_t i) {
    float x = src[i];
    __half h = __float2half_rn(x);
    hi[i] = h;
    lo[i] = __float2half_rn((x - __half2float(h)) * LO_SCALE);
}

__global__ void split_x_kernel(const float* __restrict__ x) {
    size_t i = (size_t)blockIdx.x * 256 + threadIdx.x;
    split_one(x, g_Xhi, g_Xlo, i);
}

__global__ void split_w_kernel(const float* __restrict__ Wq, const float* __restrict__ Wk,
                               const float* __restrict__ Wv, const float* __restrict__ Wo) {
    int z = blockIdx.z;
    const float* W = (z == 0) ? Wq : (z == 1) ? Wk : (z == 2) ? Wv : Wo;
    size_t i = (size_t)blockIdx.x * 256 + threadIdx.x;
    split_one(W, g_Whi + (size_t)z * D * D, g_Wlo + (size_t)z * D * D, i);
}

__global__ void rope_table_kernel(const int* __restrict__ pos) {
    int m = blockIdx.x;
    int i = threadIdx.x;  // pair index 0..31
    double f = pow(10000.0, -(double)(2 * i) / 64.0);
    float ang = (float)pos[m] * (float)f;
    float sv, cv;
    sincosf(ang, &sv, &cv);
    g_cos[m * 32 + i] = cv;
    g_sin[m * 32 + i] = sv;
}

// ---------------- split-fp16 HMMA GEMM:  Y = A @ B^T -------------------------
// CTA 128x128, 4 warps (2x2), each warp 64x64. k-chunk 32, double-buffered.
// Main combo (Ah*Bh) in f32 acc; corrections (Ah*Bl + Al*Bh) in f16 acc.
#define MM_SP    80
#define MM_MAT   (128 * MM_SP)
#define MM_STAGE (4 * MM_MAT)      // Ah, Al, Bh, Bl
#define MM_SMEM  (2 * MM_STAGE)    // 81920 B

__device__ __forceinline__ void mm_load_stage(uint32_t sb, int st, int c,
                                              const __half* A_h, const __half* A_l,
                                              const __half* B_h, const __half* B_l) {
    const __half* srcs[4] = {A_h, A_l, B_h, B_l};
    int t = threadIdx.x;
#pragma unroll
    for (int i = 0; i < 16; i++) {
        int cid = t + i * 128;
        int mi = cid >> 9;
        int r  = (cid >> 2) & 127;
        int q  = cid & 3;
        const __half* g = srcs[mi] + (size_t)r * D + c * 32 + q * 8;
        cp16(sb + st * MM_STAGE + mi * MM_MAT + r * MM_SP + q * 16, g);
    }
}

__device__ __forceinline__ void mm_stage_compute(uint32_t so, int wm, int wn, int lane,
                                                 float acc[4][8][4], uint32_t corr[4][8][2]) {
    const int lr = lane & 15, lc = lane >> 4;
#pragma unroll
    for (int ks = 0; ks < 2; ks++) {
        uint32_t a4[4][4], bh[8][2], bl[8][2], t4[4];
#pragma unroll
        for (int i = 0; i < 4; i++)
            ldsm4(so + 0 * MM_MAT + (wm * 64 + i * 16 + lr) * MM_SP + ks * 32 + lc * 16, a4[i]);
#pragma unroll
        for (int jj = 0; jj < 4; jj++) {
            ldsm4(so + 2 * MM_MAT + (wn * 64 + jj * 16 + lr) * MM_SP + ks * 32 + lc * 16, t4);
            bh[2 * jj][0] = t4[0]; bh[2 * jj][1] = t4[2];
            bh[2 * jj + 1][0] = t4[1]; bh[2 * jj + 1][1] = t4[3];
        }
        // main: Ah*Bh, f32 acc
#pragma unroll
        for (int i = 0; i < 4; i++)
#pragma unroll
            for (int j = 0; j < 8; j++)
                mma16816(acc[i][j], a4[i], bh[j][0], bh[j][1]);
#pragma unroll
        for (int jj = 0; jj < 4; jj++) {
            ldsm4(so + 3 * MM_MAT + (wn * 64 + jj * 16 + lr) * MM_SP + ks * 32 + lc * 16, t4);
            bl[2 * jj][0] = t4[0]; bl[2 * jj][1] = t4[2];
            bl[2 * jj + 1][0] = t4[1]; bl[2 * jj + 1][1] = t4[3];
        }
        // corr: Ah*Bl' (scaled), f16 acc
#pragma unroll
        for (int i = 0; i < 4; i++)
#pragma unroll
            for (int j = 0; j < 8; j++)
                mma16816h(corr[i][j], a4[i], bl[j][0], bl[j][1]);
#pragma unroll
        for (int i = 0; i < 4; i++)
            ldsm4(so + 1 * MM_MAT + (wm * 64 + i * 16 + lr) * MM_SP + ks * 32 + lc * 16, a4[i]);
        // corr: Al'*Bh (scaled), f16 acc
#pragma unroll
        for (int i = 0; i < 4; i++)
#pragma unroll
            for (int j = 0; j < 8; j++)
                mma16816h(corr[i][j], a4[i], bh[j][0], bh[j][1]);
    }
}

// mode 0: rope + fp16 hi/lo out; mode 1: fp16 hi/lo out; mode 2: fp32 out.
__device__ void mm_body(const __half* Ah, const __half* Al, const __half* Bh, const __half* Bl,
                        int mode, float* outF, __half* outH, __half* outL) {
    extern __shared__ char smem[];
    uint32_t sb = smem_u32(smem);
    const int tid = threadIdx.x, lane = tid & 31, wid = tid >> 5;
    const int wm = wid >> 1, wn = wid & 1;
    const int m0 = blockIdx.y * 128, n0 = blockIdx.x * 128;

    const __half* A_h = Ah + (size_t)m0 * D;
    const __half* A_l = Al + (size_t)m0 * D;
    const __half* B_h = Bh + (size_t)n0 * D;
    const __half* B_l = Bl + (size_t)n0 * D;

    float acc[4][8][4];
    uint32_t corr[4][8][2];
#pragma unroll
    for (int i = 0; i < 4; i++)
#pragma unroll
        for (int j = 0; j < 8; j++) {
#pragma unroll
            for (int e = 0; e < 4; e++) acc[i][j][e] = 0.0f;
            corr[i][j][0] = 0u; corr[i][j][1] = 0u;
        }

    mm_load_stage(sb, 0, 0, A_h, A_l, B_h, B_l);
    asm volatile("cp.async.commit_group;" ::: "memory");

#pragma unroll 1
    for (int c = 0; c < 32; c++) {
        int st = c & 1;
        if (c + 1 < 32) {
            mm_load_stage(sb, st ^ 1, c + 1, A_h, A_l, B_h, B_l);
            asm volatile("cp.async.commit_group;" ::: "memory");
            asm volatile("cp.async.wait_group 1;" ::: "memory");
        } else {
            asm volatile("cp.async.wait_group 0;" ::: "memory");
        }
        __syncthreads();
        mm_stage_compute(sb + st * MM_STAGE, wm, wn, lane, acc, corr);
        __syncthreads();
    }

    const int g = lane >> 2, tig = lane & 3;
#pragma unroll
    for (int i = 0; i < 4; i++)
#pragma unroll
        for (int j = 0; j < 8; j++) {
            // fold f16 corrections into f32 acc
            float2 c01 = __half22float2(*(__half2*)&corr[i][j][0]);
            float2 c23 = __half22float2(*(__half2*)&corr[i][j][1]);
            acc[i][j][0] += c01.x * INV_LO; acc[i][j][1] += c01.y * INV_LO;
            acc[i][j][2] += c23.x * INV_LO; acc[i][j][3] += c23.y * INV_LO;

            const int m = m0 + wm * 64 + i * 16 + g;
            const int n = n0 + wn * 64 + j * 8 + tig * 2;
#pragma unroll
            for (int rr = 0; rr < 2; rr++) {
                const int mm = m + rr * 8;
                float e = acc[i][j][rr * 2], o = acc[i][j][rr * 2 + 1];
                if (mode == 0) {
                    const int pidx = (n & 63) >> 1;
                    const float cv = g_cos[mm * 32 + pidx];
                    const float sv = g_sin[mm * 32 + pidx];
                    const float e2 = e * cv - o * sv;
                    const float o2 = e * sv + o * cv;
                    e = e2; o = o2;
                }
                if (mode == 2) {
                    *(float2*)(outF + (size_t)mm * D + n) = make_float2(e, o);
                } else {
                    __half he = __float2half_rn(e), ho = __float2half_rn(o);
                    float le = (e - __half2float(he)) * LO_SCALE;
                    float lo_ = (o - __half2float(ho)) * LO_SCALE;
                    *(uint32_t*)(outH + (size_t)mm * D + n) =
                        ((uint32_t)__half_as_ushort(ho) << 16) | __half_as_ushort(he);
                    *(uint32_t*)(outL + (size_t)mm * D + n) = pack_h2(le, lo_);
                }
            }
        }
}

__global__ __launch_bounds__(128, 2) void mm_qkv_kernel() {
    const int z = blockIdx.z;
    const __half* Bh = g_Whi + (size_t)z * D * D;
    const __half* Bl = g_Wlo + (size_t)z * D * D;
    __half* oh = (z == 0) ? g_Qhi : (z == 1) ? g_Khi : g_Vhi;
    __half* ol = (z == 0) ? g_Qlo : (z == 1) ? g_Klo : g_Vlo;
    mm_body(g_Xhi, g_Xlo, Bh, Bl, (z < 2) ? 0 : 1, (float*)0, oh, ol);
}

__global__ __launch_bounds__(128, 2) void mm_out_kernel(float* __restrict__ out) {
    mm_body(g_Ohi, g_Olo, g_Whi + 3ull * D * D, g_Wlo + 3ull * D * D, 2, out, (__half*)0, (__half*)0);
}

// ---------------- HMMA flash attention --------------------------------------
// CTA = 64 q rows x 1 head, 4 warps (each m16). kv tiles of 64, single buffer.
#define AT_SP   144
#define AT_MAT  (64 * AT_SP)
#define AT_SMEM (6 * AT_MAT)

__device__ __forceinline__ void at_load64(uint32_t sdst, const __half* g) {
    int t = threadIdx.x;
#pragma unroll
    for (int i = 0; i < 4; i++) {
        int cid = t + i * 128;
        int r = cid >> 3;
        int q = cid & 7;
        cp16(sdst + r * AT_SP + q * 16, g + (size_t)r * D + q * 8);
    }
}

__global__ __launch_bounds__(128) void attn_kernel() {
    extern __shared__ char smem[];
    uint32_t sb = smem_u32(smem);
    const int tid = threadIdx.x, lane = tid & 31, w = tid >> 5;
    const int qt = (int)gridDim.x - 1 - (int)blockIdx.x;   // heavy first
    const int h = blockIdx.y;
    const int qbase = qt * 64;
    const int lr = lane & 15, lc = lane >> 4;
    const int g = lane >> 2, tig = lane & 3;

    at_load64(sb + 0 * AT_MAT, g_Qhi + (size_t)qbase * D + h * HD);
    at_load64(sb + 1 * AT_MAT, g_Qlo + (size_t)qbase * D + h * HD);
    asm volatile("cp.async.commit_group;" ::: "memory");
    asm volatile("cp.async.wait_group 0;" ::: "memory");
    __syncthreads();

    uint32_t qh[4][4], ql[4][4];
#pragma unroll
    for (int ks = 0; ks < 4; ks++) {
        ldsm4(sb + 0 * AT_MAT + (w * 16 + lr) * AT_SP + ks * 32 + lc * 16, qh[ks]);
        ldsm4(sb + 1 * AT_MAT + (w * 16 + lr) * AT_SP + ks * 32 + lc * 16, ql[ks]);
    }

    float o[8][4];
#pragma unroll
    for (int j = 0; j < 8; j++)
#pragma unroll
        for (int e = 0; e < 4; e++) o[j][e] = 0.0f;
    float m0r = -1e30f, m1r = -1e30f, l0 = 0.0f, l1 = 0.0f;

#pragma unroll 1
    for (int kt = 0; kt <= qt; kt++) {
        const size_t koff = (size_t)(kt * 64) * D + h * HD;
        __syncthreads();
        at_load64(sb + 2 * AT_MAT, g_Khi + koff);
        at_load64(sb + 3 * AT_MAT, g_Klo + koff);
        at_load64(sb + 4 * AT_MAT, g_Vhi + koff);
        at_load64(sb + 5 * AT_MAT, g_Vlo + koff);
        asm volatile("cp.async.commit_group;" ::: "memory");
        asm volatile("cp.async.wait_group 0;" ::: "memory");
        __syncthreads();

        float s[8][4];
        uint32_t scorr[8][2];
#pragma unroll
        for (int j = 0; j < 8; j++) {
#pragma unroll
            for (int e = 0; e < 4; e++) s[j][e] = 0.0f;
            scorr[j][0] = 0u; scorr[j][1] = 0u;
        }

        // --- S: main Qh*Kh (f32) + corr Ql'*Kh + Qh*Kl' (f16) ---
#pragma unroll
        for (int ks = 0; ks < 4; ks++) {
            uint32_t kh[4][4];
#pragma unroll
            for (int jj = 0; jj < 4; jj++)
                ldsm4(sb + 2 * AT_MAT + (jj * 16 + lr) * AT_SP + ks * 32 + lc * 16, kh[jj]);
#pragma unroll
            for (int jj = 0; jj < 4; jj++) {
                mma16816(s[2 * jj],     qh[ks], kh[jj][0], kh[jj][2]);
                mma16816(s[2 * jj + 1], qh[ks], kh[jj][1], kh[jj][3]);
            }
#pragma unroll
            for (int jj = 0; jj < 4; jj++) {
                mma16816h(scorr[2 * jj],     ql[ks], kh[jj][0], kh[jj][2]);
                mma16816h(scorr[2 * jj + 1], ql[ks], kh[jj][1], kh[jj][3]);
            }
            uint32_t kl[4][4];
#pragma unroll
            for (int jj = 0; jj < 4; jj++)
                ldsm4(sb + 3 * AT_MAT + (jj * 16 + lr) * AT_SP + ks * 32 + lc * 16, kl[jj]);
#pragma unroll
            for (int jj = 0; jj < 4; jj++) {
                mma16816h(scorr[2 * jj],     qh[ks], kl[jj][0], kl[jj][2]);
                mma16816h(scorr[2 * jj + 1], qh[ks], kl[jj][1], kl[jj][3]);
            }
        }

        // --- fold corr, scale + causal mask ---
        const bool diag = (kt == qt);
#pragma unroll
        for (int j = 0; j < 8; j++) {
            float2 c01 = __half22float2(*(__half2*)&scorr[j][0]);
            float2 c23 = __half22float2(*(__half2*)&scorr[j][1]);
            s[j][0] += c01.x * INV_LO; s[j][1] += c01.y * INV_LO;
            s[j][2] += c23.x * INV_LO; s[j][3] += c23.y * INV_LO;
#pragma unroll
            for (int e = 0; e < 4; e++) {
                float v = s[j][e] * 0.125f;
                if (diag) {
                    const int kvc = kt * 64 + j * 8 + tig * 2 + (e & 1);
                    const int qr  = qbase + w * 16 + g + ((e >> 1) << 3);
                    if (kvc > qr) v = -1e30f;
                }
                s[j][e] = v;
            }
        }

        // --- online softmax ---
        float mx0 = -1e30f, mx1 = -1e30f;
#pragma unroll
        for (int j = 0; j < 8; j++) {
            mx0 = fmaxf(mx0, fmaxf(s[j][0], s[j][1]));
            mx1 = fmaxf(mx1, fmaxf(s[j][2], s[j][3]));
        }
        mx0 = fmaxf(mx0, __shfl_xor_sync(0xffffffffu, mx0, 1));
        mx0 = fmaxf(mx0, __shfl_xor_sync(0xffffffffu, mx0, 2));
        mx1 = fmaxf(mx1, __shfl_xor_sync(0xffffffffu, mx1, 1));
        mx1 = fmaxf(mx1, __shfl_xor_sync(0xffffffffu, mx1, 2));
        const float nm0 = fmaxf(m0r, mx0), nm1 = fmaxf(m1r, mx1);
        const float sc0 = __expf(m0r - nm0), sc1 = __expf(m1r - nm1);
        m0r = nm0; m1r = nm1;
        l0 *= sc0; l1 *= sc1;
#pragma unroll
        for (int j = 0; j < 8; j++) {
            o[j][0] *= sc0; o[j][1] *= sc0;
            o[j][2] *= sc1; o[j][3] *= sc1;
        }
#pragma unroll
        for (int j = 0; j < 8; j++) {
            s[j][0] = __expf(s[j][0] - nm0); s[j][1] = __expf(s[j][1] - nm0);
            s[j][2] = __expf(s[j][2] - nm1); s[j][3] = __expf(s[j][3] - nm1);
            l0 += s[j][0] + s[j][1];
            l1 += s[j][2] + s[j][3];
        }

        // --- O: main Ph*Vh (f32) + corr Pl'*Vh + Ph*Vl' (f16) ---
        uint32_t ocorr[8][2];
#pragma unroll
        for (int j = 0; j < 8; j++) { ocorr[j][0] = 0u; ocorr[j][1] = 0u; }

#pragma unroll
        for (int ks = 0; ks < 4; ks++) {
            uint32_t pa[4], pl[4];
#pragma unroll
            for (int hv = 0; hv < 2; hv++) {
                const float v0 = s[2 * ks + hv][0], v1 = s[2 * ks + hv][1];
                const float v2 = s[2 * ks + hv][2], v3 = s[2 * ks + hv][3];
                __half h0 = __float2half_rn(v0), h1 = __float2half_rn(v1);
                __half h2 = __float2half_rn(v2), h3 = __float2half_rn(v3);
                pa[2 * hv]     = ((uint32_t)__half_as_ushort(h1) << 16) | __half_as_ushort(h0);
                pa[2 * hv + 1] = ((uint32_t)__half_as_ushort(h3) << 16) | __half_as_ushort(h2);
                pl[2 * hv]     = pack_h2((v0 - __half2float(h0)) * LO_SCALE,
                                         (v1 - __half2float(h1)) * LO_SCALE);
                pl[2 * hv + 1] = pack_h2((v2 - __half2float(h2)) * LO_SCALE,
                                         (v3 - __half2float(h3)) * LO_SCALE);
            }
            uint32_t vh[4][4];
#pragma unroll
            for (int jj = 0; jj < 4; jj++)
                ldsm4t(sb + 4 * AT_MAT + (ks * 16 + lr) * AT_SP + jj * 32 + lc * 16, vh[jj]);
#pragma unroll
            for (int jj = 0; jj < 4; jj++) {
                mma16816(o[2 * jj],     pa, vh[jj][0], vh[jj][1]);
                mma16816(o[2 * jj + 1], pa, vh[jj][2], vh[jj][3]);
            }
#pragma unroll
            for (int jj = 0; jj < 4; jj++) {
                mma16816h(ocorr[2 * jj],     pl, vh[jj][0], vh[jj][1]);
                mma16816h(ocorr[2 * jj + 1], pl, vh[jj][2], vh[jj][3]);
            }
            uint32_t vl[4][4];
#pragma unroll
            for (int jj = 0; jj < 4; jj++)
                ldsm4t(sb + 5 * AT_MAT + (ks * 16 + lr) * AT_SP + jj * 32 + lc * 16, vl[jj]);
#pragma unroll
            for (int jj = 0; jj < 4; jj++) {
                mma16816h(ocorr[2 * jj],     pa, vl[jj][0], vl[jj][1]);
                mma16816h(ocorr[2 * jj + 1], pa, vl[jj][2], vl[jj][3]);
            }
        }
        // fold PV corrections for this tile
#pragma unroll
        for (int j = 0; j < 8; j++) {
            float2 c01 = __half22float2(*(__half2*)&ocorr[j][0]);
            float2 c23 = __half22float2(*(__half2*)&ocorr[j][1]);
            o[j][0] += c01.x * INV_LO; o[j][1] += c01.y * INV_LO;
            o[j][2] += c23.x * INV_LO; o[j][3] += c23.y * INV_LO;
        }
    }

    // --- finalize ---
    l0 += __shfl_xor_sync(0xffffffffu, l0, 1);
    l0 += __shfl_xor_sync(0xffffffffu, l0, 2);
    l1 += __shfl_xor_sync(0xffffffffu, l1, 1);
    l1 += __shfl_xor_sync(0xffffffffu, l1, 2);
    const float i0 = 1.0f / l0, i1 = 1.0f / l1;

#pragma unroll
    for (int j = 0; j < 8; j++) {
        const int n = h * HD + j * 8 + tig * 2;
#pragma unroll
        for (int rr = 0; rr < 2; rr++) {
            const int mm = qbase + w * 16 + g + rr * 8;
            const float inv = rr ? i1 : i0;
            const float e = o[j][2 * rr] * inv;
            const float od = o[j][2 * rr + 1] * inv;
            __half he = __float2half_rn(e), ho = __float2half_rn(od);
            float le = (e - __half2float(he)) * LO_SCALE;
            float lo_ = (od - __half2float(ho)) * LO_SCALE;
            *(uint32_t*)(g_Ohi + (size_t)mm * D + n) =
                ((uint32_t)__half_as_ushort(ho) << 16) | __half_as_ushort(he);
            *(uint32_t*)(g_Olo + (size_t)mm * D + n) = pack_h2(le, lo_);
        }
    }
}

// ---------------------------------------------------------------------------
extern "C" void kernel_launch(void* const* d_in, const int* in_sizes, int n_in,
                              void* d_out, int out_size) {
    (void)in_sizes; (void)n_in; (void)out_size;
    const float* x   = (const float*)d_in[0];
    const int*   pos = (const int*)  d_in[1];
    const float* Wq  = (const float*)d_in[2];
    const float* Wk  = (const float*)d_in[3];
    const float* Wv  = (const float*)d_in[4];
    const float* Wo  = (const float*)d_in[5];
    float* out = (float*)d_out;

    cudaFuncSetAttribute(mm_qkv_kernel, cudaFuncAttributeMaxDynamicSharedMemorySize, MM_SMEM);
    cudaFuncSetAttribute(mm_out_kernel, cudaFuncAttributeMaxDynamicSharedMemorySize, MM_SMEM);
    cudaFuncSetAttribute(attn_kernel, cudaFuncAttributeMaxDynamicSharedMemorySize, AT_SMEM);

    split_x_kernel<<<(S * D) / 256, 256>>>(x);
    split_w_kernel<<<dim3((D * D) / 256, 1, 4), 256>>>(Wq, Wk, Wv, Wo);
    rope_table_kernel<<<S, 32>>>(pos);

    mm_qkv_kernel<<<dim3(D / 128, S / 128, 3), 128, MM_SMEM>>>();
    attn_kernel<<<dim3(S / 64, H), 128, AT_SMEM>>>();
    mm_out_kernel<<<dim3(D / 128, S / 128, 1), 128, MM_SMEM>>>(out);
}

// round 9
// speedup vs baseline: 1.4839x; 1.3690x over previous
#include <cuda_runtime.h>
#include <cuda_fp16.h>
#include <cstdint>
#include <math.h>

#define S 4096
#define D 1024
#define H 16
#define HD 64
#define LO_SCALE 2048.0f
#define INV_LO (1.0f / 2048.0f)

// ---------------- device scratch -------------------------------------------
__device__ __half g_Xhi[(size_t)S * D], g_Xlo[(size_t)S * D];
__device__ __half g_Whi[4 * (size_t)D * D];
__device__ __half g_Qhi[(size_t)S * D], g_Qlo[(size_t)S * D];
__device__ __half g_Khi[(size_t)S * D];
__device__ __half g_Vhi[(size_t)S * D];
__device__ __half g_Ohi[(size_t)S * D], g_Olo[(size_t)S * D];
__device__ float g_cos[S * 32], g_sin[S * 32];

// ---------------- helpers ---------------------------------------------------
__device__ __forceinline__ uint32_t smem_u32(const void* p) {
    uint32_t a;
    asm("{ .reg .u64 t; cvta.to.shared.u64 t, %1; cvt.u32.u64 %0, t; }"
        : "=r"(a) : "l"(p));
    return a;
}

__device__ __forceinline__ void cp16(uint32_t saddr, const void* g) {
    asm volatile("cp.async.cg.shared.global [%0], [%1], 16;" :: "r"(saddr), "l"(g));
}

__device__ __forceinline__ void ldsm4(uint32_t a, uint32_t r[4]) {
    asm volatile("ldmatrix.sync.aligned.m8n8.x4.shared.b16 {%0,%1,%2,%3}, [%4];"
                 : "=r"(r[0]), "=r"(r[1]), "=r"(r[2]), "=r"(r[3]) : "r"(a));
}

__device__ __forceinline__ void ldsm4t(uint32_t a, uint32_t r[4]) {
    asm volatile("ldmatrix.sync.aligned.m8n8.x4.trans.shared.b16 {%0,%1,%2,%3}, [%4];"
                 : "=r"(r[0]), "=r"(r[1]), "=r"(r[2]), "=r"(r[3]) : "r"(a));
}

// f32-accumulate fp16 MMA
__device__ __forceinline__ void mma16816(float c[4], const uint32_t a[4],
                                         uint32_t b0, uint32_t b1) {
    asm("mma.sync.aligned.m16n8k16.row.col.f32.f16.f16.f32 "
        "{%0,%1,%2,%3}, {%4,%5,%6,%7}, {%8,%9}, {%0,%1,%2,%3};"
        : "+f"(c[0]), "+f"(c[1]), "+f"(c[2]), "+f"(c[3])
        : "r"(a[0]), "r"(a[1]), "r"(a[2]), "r"(a[3]), "r"(b0), "r"(b1));
}

// f16-accumulate fp16 MMA (correction path)
__device__ __forceinline__ void mma16816h(uint32_t c[2], const uint32_t a[4],
                                          uint32_t b0, uint32_t b1) {
    asm("mma.sync.aligned.m16n8k16.row.col.f16.f16.f16.f16 "
        "{%0,%1}, {%2,%3,%4,%5}, {%6,%7}, {%0,%1};"
        : "+r"(c[0]), "+r"(c[1])
        : "r"(a[0]), "r"(a[1]), "r"(a[2]), "r"(a[3]), "r"(b0), "r"(b1));
}

__device__ __forceinline__ uint32_t pack_h2(float a, float b) {
    __half2 h = __floats2half2_rn(a, b);
    return *(uint32_t*)&h;
}

// ---------------- split / rope-table kernels --------------------------------
__global__ void split_x_kernel(const float* __restrict__ x) {
    size_t i = (size_t)blockIdx.x * 256 + threadIdx.x;
    float v = x[i];
    __half h = __float2half_rn(v);
    g_Xhi[i] = h;
    g_Xlo[i] = __float2half_rn((v - __half2float(h)) * LO_SCALE);
}

__global__ void split_w_kernel(const float* __restrict__ Wq, const float* __restrict__ Wk,
                               const float* __restrict__ Wv, const float* __restrict__ Wo) {
    int z = blockIdx.z;
    const float* W = (z == 0) ? Wq : (z == 1) ? Wk : (z == 2) ? Wv : Wo;
    size_t i = (size_t)blockIdx.x * 256 + threadIdx.x;
    g_Whi[(size_t)z * D * D + i] = __float2half_rn(W[i]);
}

__global__ void rope_table_kernel(const int* __restrict__ pos) {
    int m = blockIdx.x;
    int i = threadIdx.x;  // pair index 0..31
    double f = pow(10000.0, -(double)(2 * i) / 64.0);
    float ang = (float)pos[m] * (float)f;
    float sv, cv;
    sincosf(ang, &sv, &cv);
    g_cos[m * 32 + i] = cv;
    g_sin[m * 32 + i] = sv;
}

// ---------------- split-fp16 HMMA GEMM:  Y = A @ B^T -------------------------
// CTA 128x128, 4 warps (2x2), each warp 64x64. k-chunk 32, double-buffered.
// 2-combo: Ah*Bh in f32 acc; Al'*Bh in f16 acc (Al pre-scaled x2048).
#define MM_SP    80
#define MM_MAT   (128 * MM_SP)
#define MM_STAGE (3 * MM_MAT)      // Ah, Al, Bh
#define MM_SMEM  (2 * MM_STAGE)    // 61440 B

__device__ __forceinline__ void mm_load_stage(uint32_t sb, int st, int c,
                                              const __half* A_h, const __half* A_l,
                                              const __half* B_h) {
    const __half* srcs[3] = {A_h, A_l, B_h};
    int t = threadIdx.x;
#pragma unroll
    for (int i = 0; i < 12; i++) {
        int cid = t + i * 128;                 // 0..1535
        int mi = cid >> 9;                     // matrix 0..2
        int r  = (cid >> 2) & 127;
        int q  = cid & 3;
        const __half* g = srcs[mi] + (size_t)r * D + c * 32 + q * 8;
        cp16(sb + st * MM_STAGE + mi * MM_MAT + r * MM_SP + q * 16, g);
    }
}

__device__ __forceinline__ void mm_stage_compute(uint32_t so, int wm, int wn, int lane,
                                                 float acc[4][8][4], uint32_t corr[4][8][2]) {
    const int lr = lane & 15, lc = lane >> 4;
#pragma unroll
    for (int ks = 0; ks < 2; ks++) {
        uint32_t a4[4][4], bh[8][2], t4[4];
#pragma unroll
        for (int i = 0; i < 4; i++)
            ldsm4(so + 0 * MM_MAT + (wm * 64 + i * 16 + lr) * MM_SP + ks * 32 + lc * 16, a4[i]);
#pragma unroll
        for (int jj = 0; jj < 4; jj++) {
            ldsm4(so + 2 * MM_MAT + (wn * 64 + jj * 16 + lr) * MM_SP + ks * 32 + lc * 16, t4);
            bh[2 * jj][0] = t4[0]; bh[2 * jj][1] = t4[2];
            bh[2 * jj + 1][0] = t4[1]; bh[2 * jj + 1][1] = t4[3];
        }
        // main: Ah*Bh, f32 acc
#pragma unroll
        for (int i = 0; i < 4; i++)
#pragma unroll
            for (int j = 0; j < 8; j++)
                mma16816(acc[i][j], a4[i], bh[j][0], bh[j][1]);
#pragma unroll
        for (int i = 0; i < 4; i++)
            ldsm4(so + 1 * MM_MAT + (wm * 64 + i * 16 + lr) * MM_SP + ks * 32 + lc * 16, a4[i]);
        // corr: Al'*Bh (scaled), f16 acc
#pragma unroll
        for (int i = 0; i < 4; i++)
#pragma unroll
            for (int j = 0; j < 8; j++)
                mma16816h(corr[i][j], a4[i], bh[j][0], bh[j][1]);
    }
}

// mode 0: rope + hi/lo (Q); 1: rope + hi (K); 2: hi (V); 3: fp32 (final out).
__device__ void mm_body(const __half* Ah, const __half* Al, const __half* Bh,
                        int mode, float* outF, __half* outH, __half* outL) {
    extern __shared__ char smem[];
    uint32_t sb = smem_u32(smem);
    const int tid = threadIdx.x, lane = tid & 31, wid = tid >> 5;
    const int wm = wid >> 1, wn = wid & 1;
    const int m0 = blockIdx.y * 128, n0 = blockIdx.x * 128;

    const __half* A_h = Ah + (size_t)m0 * D;
    const __half* A_l = Al + (size_t)m0 * D;
    const __half* B_h = Bh + (size_t)n0 * D;

    float acc[4][8][4];
    uint32_t corr[4][8][2];
#pragma unroll
    for (int i = 0; i < 4; i++)
#pragma unroll
        for (int j = 0; j < 8; j++) {
#pragma unroll
            for (int e = 0; e < 4; e++) acc[i][j][e] = 0.0f;
            corr[i][j][0] = 0u; corr[i][j][1] = 0u;
        }

    mm_load_stage(sb, 0, 0, A_h, A_l, B_h);
    asm volatile("cp.async.commit_group;" ::: "memory");

#pragma unroll 1
    for (int c = 0; c < 32; c++) {
        int st = c & 1;
        if (c + 1 < 32) {
            mm_load_stage(sb, st ^ 1, c + 1, A_h, A_l, B_h);
            asm volatile("cp.async.commit_group;" ::: "memory");
            asm volatile("cp.async.wait_group 1;" ::: "memory");
        } else {
            asm volatile("cp.async.wait_group 0;" ::: "memory");
        }
        __syncthreads();
        mm_stage_compute(sb + st * MM_STAGE, wm, wn, lane, acc, corr);
        __syncthreads();
    }

    const int g = lane >> 2, tig = lane & 3;
#pragma unroll
    for (int i = 0; i < 4; i++)
#pragma unroll
        for (int j = 0; j < 8; j++) {
            float2 c01 = __half22float2(*(__half2*)&corr[i][j][0]);
            float2 c23 = __half22float2(*(__half2*)&corr[i][j][1]);
            acc[i][j][0] += c01.x * INV_LO; acc[i][j][1] += c01.y * INV_LO;
            acc[i][j][2] += c23.x * INV_LO; acc[i][j][3] += c23.y * INV_LO;

            const int m = m0 + wm * 64 + i * 16 + g;
            const int n = n0 + wn * 64 + j * 8 + tig * 2;
#pragma unroll
            for (int rr = 0; rr < 2; rr++) {
                const int mm = m + rr * 8;
                float e = acc[i][j][rr * 2], o = acc[i][j][rr * 2 + 1];
                if (mode <= 1) {
                    const int pidx = (n & 63) >> 1;
                    const float cv = g_cos[mm * 32 + pidx];
                    const float sv = g_sin[mm * 32 + pidx];
                    const float e2 = e * cv - o * sv;
                    const float o2 = e * sv + o * cv;
                    e = e2; o = o2;
                }
                if (mode == 3) {
                    *(float2*)(outF + (size_t)mm * D + n) = make_float2(e, o);
                } else {
                    __half he = __float2half_rn(e), ho = __float2half_rn(o);
                    *(uint32_t*)(outH + (size_t)mm * D + n) =
                        ((uint32_t)__half_as_ushort(ho) << 16) | __half_as_ushort(he);
                    if (mode == 0) {
                        float le = (e - __half2float(he)) * LO_SCALE;
                        float lo_ = (o - __half2float(ho)) * LO_SCALE;
                        *(uint32_t*)(outL + (size_t)mm * D + n) = pack_h2(le, lo_);
                    }
                }
            }
        }
}

__global__ __launch_bounds__(128, 2) void mm_qkv_kernel() {
    const int z = blockIdx.z;
    const __half* Bh = g_Whi + (size_t)z * D * D;
    if (z == 0)      mm_body(g_Xhi, g_Xlo, Bh, 0, (float*)0, g_Qhi, g_Qlo);
    else if (z == 1) mm_body(g_Xhi, g_Xlo, Bh, 1, (float*)0, g_Khi, (__half*)0);
    else             mm_body(g_Xhi, g_Xlo, Bh, 2, (float*)0, g_Vhi, (__half*)0);
}

__global__ __launch_bounds__(128, 2) void mm_out_kernel(float* __restrict__ out) {
    mm_body(g_Ohi, g_Olo, g_Whi + 3ull * D * D, 3, out, (__half*)0, (__half*)0);
}

// ---------------- HMMA flash attention --------------------------------------
// CTA = 64 q rows x 1 head, 4 warps. kv tiles of 64 (hi only), single buffer.
#define AT_SP   144
#define AT_MAT  (64 * AT_SP)
#define AT_SMEM (4 * AT_MAT)   // Qh Ql Kh Vh = 36864 B

__device__ __forceinline__ void at_load64(uint32_t sdst, const __half* g) {
    int t = threadIdx.x;
#pragma unroll
    for (int i = 0; i < 4; i++) {
        int cid = t + i * 128;
        int r = cid >> 3;
        int q = cid & 7;
        cp16(sdst + r * AT_SP + q * 16, g + (size_t)r * D + q * 8);
    }
}

__global__ __launch_bounds__(128) void attn_kernel() {
    extern __shared__ char smem[];
    uint32_t sb = smem_u32(smem);
    const int tid = threadIdx.x, lane = tid & 31, w = tid >> 5;
    const int qt = (int)gridDim.x - 1 - (int)blockIdx.x;   // heavy first
    const int h = blockIdx.y;
    const int qbase = qt * 64;
    const int lr = lane & 15, lc = lane >> 4;
    const int g = lane >> 2, tig = lane & 3;

    at_load64(sb + 0 * AT_MAT, g_Qhi + (size_t)qbase * D + h * HD);
    at_load64(sb + 1 * AT_MAT, g_Qlo + (size_t)qbase * D + h * HD);
    asm volatile("cp.async.commit_group;" ::: "memory");
    asm volatile("cp.async.wait_group 0;" ::: "memory");
    __syncthreads();

    uint32_t qh[4][4], ql[4][4];
#pragma unroll
    for (int ks = 0; ks < 4; ks++) {
        ldsm4(sb + 0 * AT_MAT + (w * 16 + lr) * AT_SP + ks * 32 + lc * 16, qh[ks]);
        ldsm4(sb + 1 * AT_MAT + (w * 16 + lr) * AT_SP + ks * 32 + lc * 16, ql[ks]);
    }

    float o[8][4];
#pragma unroll
    for (int j = 0; j < 8; j++)
#pragma unroll
        for (int e = 0; e < 4; e++) o[j][e] = 0.0f;
    float m0r = -1e30f, m1r = -1e30f, l0 = 0.0f, l1 = 0.0f;

#pragma unroll 1
    for (int kt = 0; kt <= qt; kt++) {
        const size_t koff = (size_t)(kt * 64) * D + h * HD;
        __syncthreads();
        at_load64(sb + 2 * AT_MAT, g_Khi + koff);
        at_load64(sb + 3 * AT_MAT, g_Vhi + koff);
        asm volatile("cp.async.commit_group;" ::: "memory");
        asm volatile("cp.async.wait_group 0;" ::: "memory");
        __syncthreads();

        float s[8][4];
        uint32_t scorr[8][2];
#pragma unroll
        for (int j = 0; j < 8; j++) {
#pragma unroll
            for (int e = 0; e < 4; e++) s[j][e] = 0.0f;
            scorr[j][0] = 0u; scorr[j][1] = 0u;
        }

        // --- S: Qh*Kh (f32) + Ql'*Kh (f16 corr) ---
#pragma unroll
        for (int ks = 0; ks < 4; ks++) {
            uint32_t kh[4][4];
#pragma unroll
            for (int jj = 0; jj < 4; jj++)
                ldsm4(sb + 2 * AT_MAT + (jj * 16 + lr) * AT_SP + ks * 32 + lc * 16, kh[jj]);
#pragma unroll
            for (int jj = 0; jj < 4; jj++) {
                mma16816(s[2 * jj],     qh[ks], kh[jj][0], kh[jj][2]);
                mma16816(s[2 * jj + 1], qh[ks], kh[jj][1], kh[jj][3]);
            }
#pragma unroll
            for (int jj = 0; jj < 4; jj++) {
                mma16816h(scorr[2 * jj],     ql[ks], kh[jj][0], kh[jj][2]);
                mma16816h(scorr[2 * jj + 1], ql[ks], kh[jj][1], kh[jj][3]);
            }
        }

        // --- fold corr, scale + causal mask ---
        const bool diag = (kt == qt);
#pragma unroll
        for (int j = 0; j < 8; j++) {
            float2 c01 = __half22float2(*(__half2*)&scorr[j][0]);
            float2 c23 = __half22float2(*(__half2*)&scorr[j][1]);
            s[j][0] += c01.x * INV_LO; s[j][1] += c01.y * INV_LO;
            s[j][2] += c23.x * INV_LO; s[j][3] += c23.y * INV_LO;
#pragma unroll
            for (int e = 0; e < 4; e++) {
                float v = s[j][e] * 0.125f;
                if (diag) {
                    const int kvc = kt * 64 + j * 8 + tig * 2 + (e & 1);
                    const int qr  = qbase + w * 16 + g + ((e >> 1) << 3);
                    if (kvc > qr) v = -1e30f;
                }
                s[j][e] = v;
            }
        }

        // --- online softmax ---
        float mx0 = -1e30f, mx1 = -1e30f;
#pragma unroll
        for (int j = 0; j < 8; j++) {
            mx0 = fmaxf(mx0, fmaxf(s[j][0], s[j][1]));
            mx1 = fmaxf(mx1, fmaxf(s[j][2], s[j][3]));
        }
        mx0 = fmaxf(mx0, __shfl_xor_sync(0xffffffffu, mx0, 1));
        mx0 = fmaxf(mx0, __shfl_xor_sync(0xffffffffu, mx0, 2));
        mx1 = fmaxf(mx1, __shfl_xor_sync(0xffffffffu, mx1, 1));
        mx1 = fmaxf(mx1, __shfl_xor_sync(0xffffffffu, mx1, 2));
        const float nm0 = fmaxf(m0r, mx0), nm1 = fmaxf(m1r, mx1);
        const float sc0 = __expf(m0r - nm0), sc1 = __expf(m1r - nm1);
        m0r = nm0; m1r = nm1;
        l0 *= sc0; l1 *= sc1;
#pragma unroll
        for (int j = 0; j < 8; j++) {
            o[j][0] *= sc0; o[j][1] *= sc0;
            o[j][2] *= sc1; o[j][3] *= sc1;
        }
#pragma unroll
        for (int j = 0; j < 8; j++) {
            s[j][0] = __expf(s[j][0] - nm0); s[j][1] = __expf(s[j][1] - nm0);
            s[j][2] = __expf(s[j][2] - nm1); s[j][3] = __expf(s[j][3] - nm1);
            l0 += s[j][0] + s[j][1];
            l1 += s[j][2] + s[j][3];
        }

        // --- O: Ph*Vh (f32) + Pl'*Vh (f16 corr) ---
        uint32_t ocorr[8][2];
#pragma unroll
        for (int j = 0; j < 8; j++) { ocorr[j][0] = 0u; ocorr[j][1] = 0u; }

#pragma unroll
        for (int ks = 0; ks < 4; ks++) {
            uint32_t pa[4], pl[4];
#pragma unroll
            for (int hv = 0; hv < 2; hv++) {
                const float v0 = s[2 * ks + hv][0], v1 = s[2 * ks + hv][1];
                const float v2 = s[2 * ks + hv][2], v3 = s[2 * ks + hv][3];
                __half h0 = __float2half_rn(v0), h1 = __float2half_rn(v1);
                __half h2 = __float2half_rn(v2), h3 = __float2half_rn(v3);
                pa[2 * hv]     = ((uint32_t)__half_as_ushort(h1) << 16) | __half_as_ushort(h0);
                pa[2 * hv + 1] = ((uint32_t)__half_as_ushort(h3) << 16) | __half_as_ushort(h2);
                pl[2 * hv]     = pack_h2((v0 - __half2float(h0)) * LO_SCALE,
                                         (v1 - __half2float(h1)) * LO_SCALE);
                pl[2 * hv + 1] = pack_h2((v2 - __half2float(h2)) * LO_SCALE,
                                         (v3 - __half2float(h3)) * LO_SCALE);
            }
            uint32_t vh[4][4];
#pragma unroll
            for (int jj = 0; jj < 4; jj++)
                ldsm4t(sb + 3 * AT_MAT + (ks * 16 + lr) * AT_SP + jj * 32 + lc * 16, vh[jj]);
#pragma unroll
            for (int jj = 0; jj < 4; jj++) {
                mma16816(o[2 * jj],     pa, vh[jj][0], vh[jj][1]);
                mma16816(o[2 * jj + 1], pa, vh[jj][2], vh[jj][3]);
            }
#pragma unroll
            for (int jj = 0; jj < 4; jj++) {
                mma16816h(ocorr[2 * jj],     pl, vh[jj][0], vh[jj][1]);
                mma16816h(ocorr[2 * jj + 1], pl, vh[jj][2], vh[jj][3]);
            }
        }
#pragma unroll
        for (int j = 0; j < 8; j++) {
            float2 c01 = __half22float2(*(__half2*)&ocorr[j][0]);
            float2 c23 = __half22float2(*(__half2*)&ocorr[j][1]);
            o[j][0] += c01.x * INV_LO; o[j][1] += c01.y * INV_LO;
            o[j][2] += c23.x * INV_LO; o[j][3] += c23.y * INV_LO;
        }
    }

    // --- finalize ---
    l0 += __shfl_xor_sync(0xffffffffu, l0, 1);
    l0 += __shfl_xor_sync(0xffffffffu, l0, 2);
    l1 += __shfl_xor_sync(0xffffffffu, l1, 1);
    l1 += __shfl_xor_sync(0xffffffffu, l1, 2);
    const float i0 = 1.0f / l0, i1 = 1.0f / l1;

#pragma unroll
    for (int j = 0; j < 8; j++) {
        const int n = h * HD + j * 8 + tig * 2;
#pragma unroll
        for (int rr = 0; rr < 2; rr++) {
            const int mm = qbase + w * 16 + g + rr * 8;
            const float inv = rr ? i1 : i0;
            const float e = o[j][2 * rr] * inv;
            const float od = o[j][2 * rr + 1] * inv;
            __half he = __float2half_rn(e), ho = __float2half_rn(od);
            float le = (e - __half2float(he)) * LO_SCALE;
            float lo_ = (od - __half2float(ho)) * LO_SCALE;
            *(uint32_t*)(g_Ohi + (size_t)mm * D + n) =
                ((uint32_t)__half_as_ushort(ho) << 16) | __half_as_ushort(he);
            *(uint32_t*)(g_Olo + (size_t)mm * D + n) = pack_h2(le, lo_);
        }
    }
}

// ---------------------------------------------------------------------------
extern "C" void kernel_launch(void* const* d_in, const int* in_sizes, int n_in,
                              void* d_out, int out_size) {
    (void)in_sizes; (void)n_in; (void)out_size;
    const float* x   = (const float*)d_in[0];
    const int*   pos = (const int*)  d_in[1];
    const float* Wq  = (const float*)d_in[2];
    const float* Wk  = (const float*)d_in[3];
    const float* Wv  = (const float*)d_in[4];
    const float* Wo  = (const float*)d_in[5];
    float* out = (float*)d_out;

    cudaFuncSetAttribute(mm_qkv_kernel, cudaFuncAttributeMaxDynamicSharedMemorySize, MM_SMEM);
    cudaFuncSetAttribute(mm_out_kernel, cudaFuncAttributeMaxDynamicSharedMemorySize, MM_SMEM);
    cudaFuncSetAttribute(attn_kernel, cudaFuncAttributeMaxDynamicSharedMemorySize, AT_SMEM);

    split_x_kernel<<<(S * D) / 256, 256>>>(x);
    split_w_kernel<<<dim3((D * D) / 256, 1, 4), 256>>>(Wq, Wk, Wv, Wo);
    rope_table_kernel<<<S, 32>>>(pos);

    mm_qkv_kernel<<<dim3(D / 128, S / 128, 3), 128, MM_SMEM>>>();
    attn_kernel<<<dim3(S / 64, H), 128, AT_SMEM>>>();
    mm_out_kernel<<<dim3(D / 128, S / 128, 1), 128, MM_SMEM>>>(out);
}

// round 10
// speedup vs baseline: 1.8800x; 1.2670x over previous
#include <cuda_runtime.h>
#include <cuda_fp16.h>
#include <cstdint>
#include <math.h>

#define S 4096
#define D 1024
#define H 16
#define HD 64
#define LO_SCALE 2048.0f
#define INV_LO (1.0f / 2048.0f)

// ---------------- device scratch -------------------------------------------
__device__ __half g_Xhi[(size_t)S * D], g_Xlo[(size_t)S * D];
__device__ __half g_Whi[4 * (size_t)D * D];
__device__ __half g_Qhi[(size_t)S * D], g_Qlo[(size_t)S * D];
__device__ __half g_Khi[(size_t)S * D];
__device__ __half g_Vhi[(size_t)S * D];
__device__ __half g_Ohi[(size_t)S * D], g_Olo[(size_t)S * D];
__device__ float g_cos[S * 32], g_sin[S * 32];

// ---------------- helpers ---------------------------------------------------
__device__ __forceinline__ uint32_t smem_u32(const void* p) {
    uint32_t a;
    asm("{ .reg .u64 t; cvta.to.shared.u64 t, %1; cvt.u32.u64 %0, t; }"
        : "=r"(a) : "l"(p));
    return a;
}

__device__ __forceinline__ void cp16(uint32_t saddr, const void* g) {
    asm volatile("cp.async.cg.shared.global [%0], [%1], 16;" :: "r"(saddr), "l"(g));
}

__device__ __forceinline__ void ldsm4(uint32_t a, uint32_t r[4]) {
    asm volatile("ldmatrix.sync.aligned.m8n8.x4.shared.b16 {%0,%1,%2,%3}, [%4];"
                 : "=r"(r[0]), "=r"(r[1]), "=r"(r[2]), "=r"(r[3]) : "r"(a));
}

__device__ __forceinline__ void ldsm4t(uint32_t a, uint32_t r[4]) {
    asm volatile("ldmatrix.sync.aligned.m8n8.x4.trans.shared.b16 {%0,%1,%2,%3}, [%4];"
                 : "=r"(r[0]), "=r"(r[1]), "=r"(r[2]), "=r"(r[3]) : "r"(a));
}

// f32-accumulate fp16 MMA
__device__ __forceinline__ void mma16816(float c[4], const uint32_t a[4],
                                         uint32_t b0, uint32_t b1) {
    asm("mma.sync.aligned.m16n8k16.row.col.f32.f16.f16.f32 "
        "{%0,%1,%2,%3}, {%4,%5,%6,%7}, {%8,%9}, {%0,%1,%2,%3};"
        : "+f"(c[0]), "+f"(c[1]), "+f"(c[2]), "+f"(c[3])
        : "r"(a[0]), "r"(a[1]), "r"(a[2]), "r"(a[3]), "r"(b0), "r"(b1));
}

// f16-accumulate fp16 MMA (correction path)
__device__ __forceinline__ void mma16816h(uint32_t c[2], const uint32_t a[4],
                                          uint32_t b0, uint32_t b1) {
    asm("mma.sync.aligned.m16n8k16.row.col.f16.f16.f16.f16 "
        "{%0,%1}, {%2,%3,%4,%5}, {%6,%7}, {%0,%1};"
        : "+r"(c[0]), "+r"(c[1])
        : "r"(a[0]), "r"(a[1]), "r"(a[2]), "r"(a[3]), "r"(b0), "r"(b1));
}

__device__ __forceinline__ uint32_t pack_h2(float a, float b) {
    __half2 h = __floats2half2_rn(a, b);
    return *(uint32_t*)&h;
}

// ---------------- split / rope-table kernels --------------------------------
__global__ void split_x_kernel(const float* __restrict__ x) {
    size_t i = (size_t)blockIdx.x * 256 + threadIdx.x;
    float v = x[i];
    __half h = __float2half_rn(v);
    g_Xhi[i] = h;
    g_Xlo[i] = __float2half_rn((v - __half2float(h)) * LO_SCALE);
}

__global__ void split_w_kernel(const float* __restrict__ Wq, const float* __restrict__ Wk,
                               const float* __restrict__ Wv, const float* __restrict__ Wo) {
    int z = blockIdx.z;
    const float* W = (z == 0) ? Wq : (z == 1) ? Wk : (z == 2) ? Wv : Wo;
    size_t i = (size_t)blockIdx.x * 256 + threadIdx.x;
    g_Whi[(size_t)z * D * D + i] = __float2half_rn(W[i]);
}

__global__ void rope_table_kernel(const int* __restrict__ pos) {
    int m = blockIdx.x;
    int i = threadIdx.x;  // pair index 0..31
    double f = pow(10000.0, -(double)(2 * i) / 64.0);
    float ang = (float)pos[m] * (float)f;
    float sv, cv;
    sincosf(ang, &sv, &cv);
    g_cos[m * 32 + i] = cv;
    g_sin[m * 32 + i] = sv;
}

// ---------------- split-fp16 HMMA GEMM:  Y = A @ B^T -------------------------
// CTA 128x128, 4 warps (2x2), each warp 64x64. k-chunk 32, double-buffered.
// CORR=true: Ah*Bh (f32) + Al'*Bh (f16, Al pre-scaled). CORR=false: Ah*Bh only.
#define MM_SP    80
#define MM_MAT   (128 * MM_SP)
#define MM_STAGE (3 * MM_MAT)      // Ah, Al, Bh slots (Al unused when !CORR)
#define MM_SMEM  (2 * MM_STAGE)    // 61440 B

template<bool CORR>
__device__ __forceinline__ void mm_load_stage(uint32_t sb, int st, int c,
                                              const __half* A_h, const __half* A_l,
                                              const __half* B_h) {
    int t = threadIdx.x;
    if (CORR) {
        const __half* srcs[3] = {A_h, A_l, B_h};
#pragma unroll
        for (int i = 0; i < 12; i++) {
            int cid = t + i * 128;
            int mi = cid >> 9;
            int r  = (cid >> 2) & 127;
            int q  = cid & 3;
            cp16(sb + st * MM_STAGE + mi * MM_MAT + r * MM_SP + q * 16,
                 srcs[mi] + (size_t)r * D + c * 32 + q * 8);
        }
    } else {
        const __half* srcs[2] = {A_h, B_h};
#pragma unroll
        for (int i = 0; i < 8; i++) {
            int cid = t + i * 128;
            int mi = cid >> 9;                 // 0 -> Ah, 1 -> Bh
            int r  = (cid >> 2) & 127;
            int q  = cid & 3;
            cp16(sb + st * MM_STAGE + mi * 2 * MM_MAT + r * MM_SP + q * 16,
                 srcs[mi] + (size_t)r * D + c * 32 + q * 8);
        }
    }
}

template<bool CORR>
__device__ __forceinline__ void mm_stage_compute(uint32_t so, int wm, int wn, int lane,
                                                 float acc[4][8][4], uint32_t corr[4][8][2]) {
    const int lr = lane & 15, lc = lane >> 4;
#pragma unroll
    for (int ks = 0; ks < 2; ks++) {
        uint32_t a4[4][4], bh[8][2], t4[4];
#pragma unroll
        for (int i = 0; i < 4; i++)
            ldsm4(so + 0 * MM_MAT + (wm * 64 + i * 16 + lr) * MM_SP + ks * 32 + lc * 16, a4[i]);
#pragma unroll
        for (int jj = 0; jj < 4; jj++) {
            ldsm4(so + 2 * MM_MAT + (wn * 64 + jj * 16 + lr) * MM_SP + ks * 32 + lc * 16, t4);
            bh[2 * jj][0] = t4[0]; bh[2 * jj][1] = t4[2];
            bh[2 * jj + 1][0] = t4[1]; bh[2 * jj + 1][1] = t4[3];
        }
        // main: Ah*Bh, f32 acc
#pragma unroll
        for (int i = 0; i < 4; i++)
#pragma unroll
            for (int j = 0; j < 8; j++)
                mma16816(acc[i][j], a4[i], bh[j][0], bh[j][1]);
        if (CORR) {
#pragma unroll
            for (int i = 0; i < 4; i++)
                ldsm4(so + 1 * MM_MAT + (wm * 64 + i * 16 + lr) * MM_SP + ks * 32 + lc * 16, a4[i]);
#pragma unroll
            for (int i = 0; i < 4; i++)
#pragma unroll
                for (int j = 0; j < 8; j++)
                    mma16816h(corr[i][j], a4[i], bh[j][0], bh[j][1]);
        }
    }
}

// mode 0: rope + hi/lo (Q); 1: rope + hi (K); 2: hi (V); 3: fp32 (final out).
template<bool CORR>
__device__ void mm_body(const __half* Ah, const __half* Al, const __half* Bh,
                        int mode, float* outF, __half* outH, __half* outL) {
    extern __shared__ char smem[];
    uint32_t sb = smem_u32(smem);
    const int tid = threadIdx.x, lane = tid & 31, wid = tid >> 5;
    const int wm = wid >> 1, wn = wid & 1;
    const int m0 = blockIdx.y * 128, n0 = blockIdx.x * 128;

    const __half* A_h = Ah + (size_t)m0 * D;
    const __half* A_l = CORR ? Al + (size_t)m0 * D : (const __half*)0;
    const __half* B_h = Bh + (size_t)n0 * D;

    float acc[4][8][4];
    uint32_t corr[4][8][2];
#pragma unroll
    for (int i = 0; i < 4; i++)
#pragma unroll
        for (int j = 0; j < 8; j++) {
#pragma unroll
            for (int e = 0; e < 4; e++) acc[i][j][e] = 0.0f;
            corr[i][j][0] = 0u; corr[i][j][1] = 0u;
        }

    mm_load_stage<CORR>(sb, 0, 0, A_h, A_l, B_h);
    asm volatile("cp.async.commit_group;" ::: "memory");

#pragma unroll 1
    for (int c = 0; c < 32; c++) {
        int st = c & 1;
        if (c + 1 < 32) {
            mm_load_stage<CORR>(sb, st ^ 1, c + 1, A_h, A_l, B_h);
            asm volatile("cp.async.commit_group;" ::: "memory");
            asm volatile("cp.async.wait_group 1;" ::: "memory");
        } else {
            asm volatile("cp.async.wait_group 0;" ::: "memory");
        }
        __syncthreads();
        mm_stage_compute<CORR>(sb + st * MM_STAGE, wm, wn, lane, acc, corr);
        __syncthreads();
    }

    const int g = lane >> 2, tig = lane & 3;
#pragma unroll
    for (int i = 0; i < 4; i++)
#pragma unroll
        for (int j = 0; j < 8; j++) {
            if (CORR) {
                float2 c01 = __half22float2(*(__half2*)&corr[i][j][0]);
                float2 c23 = __half22float2(*(__half2*)&corr[i][j][1]);
                acc[i][j][0] += c01.x * INV_LO; acc[i][j][1] += c01.y * INV_LO;
                acc[i][j][2] += c23.x * INV_LO; acc[i][j][3] += c23.y * INV_LO;
            }
            const int m = m0 + wm * 64 + i * 16 + g;
            const int n = n0 + wn * 64 + j * 8 + tig * 2;
#pragma unroll
            for (int rr = 0; rr < 2; rr++) {
                const int mm = m + rr * 8;
                float e = acc[i][j][rr * 2], o = acc[i][j][rr * 2 + 1];
                if (mode <= 1) {
                    const int pidx = (n & 63) >> 1;
                    const float cv = g_cos[mm * 32 + pidx];
                    const float sv = g_sin[mm * 32 + pidx];
                    const float e2 = e * cv - o * sv;
                    const float o2 = e * sv + o * cv;
                    e = e2; o = o2;
                }
                if (mode == 3) {
                    *(float2*)(outF + (size_t)mm * D + n) = make_float2(e, o);
                } else {
                    __half he = __float2half_rn(e), ho = __float2half_rn(o);
                    *(uint32_t*)(outH + (size_t)mm * D + n) =
                        ((uint32_t)__half_as_ushort(ho) << 16) | __half_as_ushort(he);
                    if (mode == 0) {
                        float le = (e - __half2float(he)) * LO_SCALE;
                        float lo_ = (o - __half2float(ho)) * LO_SCALE;
                        *(uint32_t*)(outL + (size_t)mm * D + n) = pack_h2(le, lo_);
                    }
                }
            }
        }
}

__global__ __launch_bounds__(128, 2) void mm_qkv_kernel() {
    const int z = blockIdx.z;
    const __half* Bh = g_Whi + (size_t)z * D * D;
    if (z == 0)      mm_body<true >(g_Xhi, g_Xlo, Bh, 0, (float*)0, g_Qhi, g_Qlo);
    else if (z == 1) mm_body<false>(g_Xhi, (const __half*)0, Bh, 1, (float*)0, g_Khi, (__half*)0);
    else             mm_body<false>(g_Xhi, (const __half*)0, Bh, 2, (float*)0, g_Vhi, (__half*)0);
}

__global__ __launch_bounds__(128, 2) void mm_out_kernel(float* __restrict__ out) {
    mm_body<true>(g_Ohi, g_Olo, g_Whi + 3ull * D * D, 3, out, (__half*)0, (__half*)0);
}

// ---------------- HMMA flash attention --------------------------------------
// CTA = 64 q rows x 1 head, 4 warps. kv tiles of 64 (hi only), single buffer.
// S: Qh*Kh (f32) + Ql'*Kh (f16 corr). PV: Ph*Vh only (f32).
#define AT_SP   144
#define AT_MAT  (64 * AT_SP)
#define AT_SMEM (4 * AT_MAT)   // Qh Ql Kh Vh = 36864 B

__device__ __forceinline__ void at_load64(uint32_t sdst, const __half* g) {
    int t = threadIdx.x;
#pragma unroll
    for (int i = 0; i < 4; i++) {
        int cid = t + i * 128;
        int r = cid >> 3;
        int q = cid & 7;
        cp16(sdst + r * AT_SP + q * 16, g + (size_t)r * D + q * 8);
    }
}

__global__ __launch_bounds__(128) void attn_kernel() {
    extern __shared__ char smem[];
    uint32_t sb = smem_u32(smem);
    const int tid = threadIdx.x, lane = tid & 31, w = tid >> 5;
    const int qt = (int)gridDim.x - 1 - (int)blockIdx.x;   // heavy first
    const int h = blockIdx.y;
    const int qbase = qt * 64;
    const int lr = lane & 15, lc = lane >> 4;
    const int g = lane >> 2, tig = lane & 3;

    at_load64(sb + 0 * AT_MAT, g_Qhi + (size_t)qbase * D + h * HD);
    at_load64(sb + 1 * AT_MAT, g_Qlo + (size_t)qbase * D + h * HD);
    asm volatile("cp.async.commit_group;" ::: "memory");
    asm volatile("cp.async.wait_group 0;" ::: "memory");
    __syncthreads();

    uint32_t qh[4][4], ql[4][4];
#pragma unroll
    for (int ks = 0; ks < 4; ks++) {
        ldsm4(sb + 0 * AT_MAT + (w * 16 + lr) * AT_SP + ks * 32 + lc * 16, qh[ks]);
        ldsm4(sb + 1 * AT_MAT + (w * 16 + lr) * AT_SP + ks * 32 + lc * 16, ql[ks]);
    }

    float o[8][4];
#pragma unroll
    for (int j = 0; j < 8; j++)
#pragma unroll
        for (int e = 0; e < 4; e++) o[j][e] = 0.0f;
    float m0r = -1e30f, m1r = -1e30f, l0 = 0.0f, l1 = 0.0f;

#pragma unroll 1
    for (int kt = 0; kt <= qt; kt++) {
        const size_t koff = (size_t)(kt * 64) * D + h * HD;
        __syncthreads();
        at_load64(sb + 2 * AT_MAT, g_Khi + koff);
        at_load64(sb + 3 * AT_MAT, g_Vhi + koff);
        asm volatile("cp.async.commit_group;" ::: "memory");
        asm volatile("cp.async.wait_group 0;" ::: "memory");
        __syncthreads();

        float s[8][4];
        uint32_t scorr[8][2];
#pragma unroll
        for (int j = 0; j < 8; j++) {
#pragma unroll
            for (int e = 0; e < 4; e++) s[j][e] = 0.0f;
            scorr[j][0] = 0u; scorr[j][1] = 0u;
        }

        // --- S: Qh*Kh (f32) + Ql'*Kh (f16 corr) ---
#pragma unroll
        for (int ks = 0; ks < 4; ks++) {
            uint32_t kh[4][4];
#pragma unroll
            for (int jj = 0; jj < 4; jj++)
                ldsm4(sb + 2 * AT_MAT + (jj * 16 + lr) * AT_SP + ks * 32 + lc * 16, kh[jj]);
#pragma unroll
            for (int jj = 0; jj < 4; jj++) {
                mma16816(s[2 * jj],     qh[ks], kh[jj][0], kh[jj][2]);
                mma16816(s[2 * jj + 1], qh[ks], kh[jj][1], kh[jj][3]);
            }
#pragma unroll
            for (int jj = 0; jj < 4; jj++) {
                mma16816h(scorr[2 * jj],     ql[ks], kh[jj][0], kh[jj][2]);
                mma16816h(scorr[2 * jj + 1], ql[ks], kh[jj][1], kh[jj][3]);
            }
        }

        // --- fold corr, scale + causal mask ---
        const bool diag = (kt == qt);
#pragma unroll
        for (int j = 0; j < 8; j++) {
            float2 c01 = __half22float2(*(__half2*)&scorr[j][0]);
            float2 c23 = __half22float2(*(__half2*)&scorr[j][1]);
            s[j][0] += c01.x * INV_LO; s[j][1] += c01.y * INV_LO;
            s[j][2] += c23.x * INV_LO; s[j][3] += c23.y * INV_LO;
#pragma unroll
            for (int e = 0; e < 4; e++) {
                float v = s[j][e] * 0.125f;
                if (diag) {
                    const int kvc = kt * 64 + j * 8 + tig * 2 + (e & 1);
                    const int qr  = qbase + w * 16 + g + ((e >> 1) << 3);
                    if (kvc > qr) v = -1e30f;
                }
                s[j][e] = v;
            }
        }

        // --- online softmax ---
        float mx0 = -1e30f, mx1 = -1e30f;
#pragma unroll
        for (int j = 0; j < 8; j++) {
            mx0 = fmaxf(mx0, fmaxf(s[j][0], s[j][1]));
            mx1 = fmaxf(mx1, fmaxf(s[j][2], s[j][3]));
        }
        mx0 = fmaxf(mx0, __shfl_xor_sync(0xffffffffu, mx0, 1));
        mx0 = fmaxf(mx0, __shfl_xor_sync(0xffffffffu, mx0, 2));
        mx1 = fmaxf(mx1, __shfl_xor_sync(0xffffffffu, mx1, 1));
        mx1 = fmaxf(mx1, __shfl_xor_sync(0xffffffffu, mx1, 2));
        const float nm0 = fmaxf(m0r, mx0), nm1 = fmaxf(m1r, mx1);
        const float sc0 = __expf(m0r - nm0), sc1 = __expf(m1r - nm1);
        m0r = nm0; m1r = nm1;
        l0 *= sc0; l1 *= sc1;
#pragma unroll
        for (int j = 0; j < 8; j++) {
            o[j][0] *= sc0; o[j][1] *= sc0;
            o[j][2] *= sc1; o[j][3] *= sc1;
        }
#pragma unroll
        for (int j = 0; j < 8; j++) {
            s[j][0] = __expf(s[j][0] - nm0); s[j][1] = __expf(s[j][1] - nm0);
            s[j][2] = __expf(s[j][2] - nm1); s[j][3] = __expf(s[j][3] - nm1);
            l0 += s[j][0] + s[j][1];
            l1 += s[j][2] + s[j][3];
        }

        // --- O: Ph*Vh (f32) only ---
#pragma unroll
        for (int ks = 0; ks < 4; ks++) {
            uint32_t pa[4];
#pragma unroll
            for (int hv = 0; hv < 2; hv++) {
                pa[2 * hv]     = pack_h2(s[2 * ks + hv][0], s[2 * ks + hv][1]);
                pa[2 * hv + 1] = pack_h2(s[2 * ks + hv][2], s[2 * ks + hv][3]);
            }
            uint32_t vh[4][4];
#pragma unroll
            for (int jj = 0; jj < 4; jj++)
                ldsm4t(sb + 3 * AT_MAT + (ks * 16 + lr) * AT_SP + jj * 32 + lc * 16, vh[jj]);
#pragma unroll
            for (int jj = 0; jj < 4; jj++) {
                mma16816(o[2 * jj],     pa, vh[jj][0], vh[jj][1]);
                mma16816(o[2 * jj + 1], pa, vh[jj][2], vh[jj][3]);
            }
        }
    }

    // --- finalize ---
    l0 += __shfl_xor_sync(0xffffffffu, l0, 1);
    l0 += __shfl_xor_sync(0xffffffffu, l0, 2);
    l1 += __shfl_xor_sync(0xffffffffu, l1, 1);
    l1 += __shfl_xor_sync(0xffffffffu, l1, 2);
    const float i0 = 1.0f / l0, i1 = 1.0f / l1;

#pragma unroll
    for (int j = 0; j < 8; j++) {
        const int n = h * HD + j * 8 + tig * 2;
#pragma unroll
        for (int rr = 0; rr < 2; rr++) {
            const int mm = qbase + w * 16 + g + rr * 8;
            const float inv = rr ? i1 : i0;
            const float e = o[j][2 * rr] * inv;
            const float od = o[j][2 * rr + 1] * inv;
            __half he = __float2half_rn(e), ho = __float2half_rn(od);
            float le = (e - __half2float(he)) * LO_SCALE;
            float lo_ = (od - __half2float(ho)) * LO_SCALE;
            *(uint32_t*)(g_Ohi + (size_t)mm * D + n) =
                ((uint32_t)__half_as_ushort(ho) << 16) | __half_as_ushort(he);
            *(uint32_t*)(g_Olo + (size_t)mm * D + n) = pack_h2(le, lo_);
        }
    }
}

// ---------------------------------------------------------------------------
extern "C" void kernel_launch(void* const* d_in, const int* in_sizes, int n_in,
                              void* d_out, int out_size) {
    (void)in_sizes; (void)n_in; (void)out_size;
    const float* x   = (const float*)d_in[0];
    const int*   pos = (const int*)  d_in[1];
    const float* Wq  = (const float*)d_in[2];
    const float* Wk  = (const float*)d_in[3];
    const float* Wv  = (const float*)d_in[4];
    const float* Wo  = (const float*)d_in[5];
    float* out = (float*)d_out;

    cudaFuncSetAttribute(mm_qkv_kernel, cudaFuncAttributeMaxDynamicSharedMemorySize, MM_SMEM);
    cudaFuncSetAttribute(mm_out_kernel, cudaFuncAttributeMaxDynamicSharedMemorySize, MM_SMEM);
    cudaFuncSetAttribute(attn_kernel, cudaFuncAttributeMaxDynamicSharedMemorySize, AT_SMEM);

    split_x_kernel<<<(S * D) / 256, 256>>>(x);
    split_w_kernel<<<dim3((D * D) / 256, 1, 4), 256>>>(Wq, Wk, Wv, Wo);
    rope_table_kernel<<<S, 32>>>(pos);

    mm_qkv_kernel<<<dim3(D / 128, S / 128, 3), 128, MM_SMEM>>>();
    attn_kernel<<<dim3(S / 64, H), 128, AT_SMEM>>>();
    mm_out_kernel<<<dim3(D / 128, S / 128, 1), 128, MM_SMEM>>>(out);
}

// round 11
// speedup vs baseline: 2.0240x; 1.0766x over previous
#include <cuda_runtime.h>
#include <cuda_fp16.h>
#include <cstdint>
#include <math.h>

#define S 4096
#define D 1024
#define H 16
#define HD 64
#define LO_SCALE 2048.0f
#define INV_LO (1.0f / 2048.0f)

// ---------------- device scratch -------------------------------------------
__device__ __half g_Xhi[(size_t)S * D], g_Xlo[(size_t)S * D];
__device__ __half g_Whi[4 * (size_t)D * D];
__device__ __half g_Qhi[(size_t)S * D], g_Qlo[(size_t)S * D];
__device__ __half g_Khi[(size_t)S * D];
__device__ __half g_Vhi[(size_t)S * D];
__device__ __half g_Ohi[(size_t)S * D];
__device__ float g_cos[S * 32], g_sin[S * 32];

// ---------------- helpers ---------------------------------------------------
__device__ __forceinline__ uint32_t smem_u32(const void* p) {
    uint32_t a;
    asm("{ .reg .u64 t; cvta.to.shared.u64 t, %1; cvt.u32.u64 %0, t; }"
        : "=r"(a) : "l"(p));
    return a;
}

__device__ __forceinline__ void cp16(uint32_t saddr, const void* g) {
    asm volatile("cp.async.cg.shared.global [%0], [%1], 16;" :: "r"(saddr), "l"(g));
}

__device__ __forceinline__ void ldsm4(uint32_t a, uint32_t r[4]) {
    asm volatile("ldmatrix.sync.aligned.m8n8.x4.shared.b16 {%0,%1,%2,%3}, [%4];"
                 : "=r"(r[0]), "=r"(r[1]), "=r"(r[2]), "=r"(r[3]) : "r"(a));
}

__device__ __forceinline__ void ldsm4t(uint32_t a, uint32_t r[4]) {
    asm volatile("ldmatrix.sync.aligned.m8n8.x4.trans.shared.b16 {%0,%1,%2,%3}, [%4];"
                 : "=r"(r[0]), "=r"(r[1]), "=r"(r[2]), "=r"(r[3]) : "r"(a));
}

// f32-accumulate fp16 MMA
__device__ __forceinline__ void mma16816(float c[4], const uint32_t a[4],
                                         uint32_t b0, uint32_t b1) {
    asm("mma.sync.aligned.m16n8k16.row.col.f32.f16.f16.f32 "
        "{%0,%1,%2,%3}, {%4,%5,%6,%7}, {%8,%9}, {%0,%1,%2,%3};"
        : "+f"(c[0]), "+f"(c[1]), "+f"(c[2]), "+f"(c[3])
        : "r"(a[0]), "r"(a[1]), "r"(a[2]), "r"(a[3]), "r"(b0), "r"(b1));
}

// f16-accumulate fp16 MMA (correction path)
__device__ __forceinline__ void mma16816h(uint32_t c[2], const uint32_t a[4],
                                          uint32_t b0, uint32_t b1) {
    asm("mma.sync.aligned.m16n8k16.row.col.f16.f16.f16.f16 "
        "{%0,%1}, {%2,%3,%4,%5}, {%6,%7}, {%0,%1};"
        : "+r"(c[0]), "+r"(c[1])
        : "r"(a[0]), "r"(a[1]), "r"(a[2]), "r"(a[3]), "r"(b0), "r"(b1));
}

__device__ __forceinline__ uint32_t pack_h2(float a, float b) {
    __half2 h = __floats2half2_rn(a, b);
    return *(uint32_t*)&h;
}

// ---------------- split / rope-table kernels --------------------------------
__global__ void split_x_kernel(const float* __restrict__ x) {
    size_t i = (size_t)blockIdx.x * 256 + threadIdx.x;
    float v = x[i];
    __half h = __float2half_rn(v);
    g_Xhi[i] = h;
    g_Xlo[i] = __float2half_rn((v - __half2float(h)) * LO_SCALE);
}

__global__ void split_w_kernel(const float* __restrict__ Wq, const float* __restrict__ Wk,
                               const float* __restrict__ Wv, const float* __restrict__ Wo) {
    int z = blockIdx.z;
    const float* W = (z == 0) ? Wq : (z == 1) ? Wk : (z == 2) ? Wv : Wo;
    size_t i = (size_t)blockIdx.x * 256 + threadIdx.x;
    g_Whi[(size_t)z * D * D + i] = __float2half_rn(W[i]);
}

__global__ void rope_table_kernel(const int* __restrict__ pos) {
    int m = blockIdx.x;
    int i = threadIdx.x;  // pair index 0..31
    double f = pow(10000.0, -(double)(2 * i) / 64.0);
    float ang = (float)pos[m] * (float)f;
    float sv, cv;
    sincosf(ang, &sv, &cv);
    g_cos[m * 32 + i] = cv;
    g_sin[m * 32 + i] = sv;
}

// ---------------- split-fp16 HMMA GEMM:  Y = A @ B^T -------------------------
// CTA 128x128, 4 warps (2x2), each warp 64x64. k-chunk 32, double-buffered.
// CORR=true: Ah*Bh (f32) + Al'*Bh (f16, Al pre-scaled). CORR=false: Ah*Bh only.
#define MM_SP    80
#define MM_MAT   (128 * MM_SP)
#define MM_STAGE (3 * MM_MAT)      // Ah, Al, Bh slots (Al unused when !CORR)
#define MM_SMEM  (2 * MM_STAGE)    // 61440 B

template<bool CORR>
__device__ __forceinline__ void mm_load_stage(uint32_t sb, int st, int c,
                                              const __half* A_h, const __half* A_l,
                                              const __half* B_h) {
    int t = threadIdx.x;
    if (CORR) {
        const __half* srcs[3] = {A_h, A_l, B_h};
#pragma unroll
        for (int i = 0; i < 12; i++) {
            int cid = t + i * 128;
            int mi = cid >> 9;
            int r  = (cid >> 2) & 127;
            int q  = cid & 3;
            cp16(sb + st * MM_STAGE + mi * MM_MAT + r * MM_SP + q * 16,
                 srcs[mi] + (size_t)r * D + c * 32 + q * 8);
        }
    } else {
        const __half* srcs[2] = {A_h, B_h};
#pragma unroll
        for (int i = 0; i < 8; i++) {
            int cid = t + i * 128;
            int mi = cid >> 9;                 // 0 -> Ah, 1 -> Bh
            int r  = (cid >> 2) & 127;
            int q  = cid & 3;
            cp16(sb + st * MM_STAGE + mi * 2 * MM_MAT + r * MM_SP + q * 16,
                 srcs[mi] + (size_t)r * D + c * 32 + q * 8);
        }
    }
}

template<bool CORR>
__device__ __forceinline__ void mm_stage_compute(uint32_t so, int wm, int wn, int lane,
                                                 float acc[4][8][4], uint32_t corr[4][8][2]) {
    const int lr = lane & 15, lc = lane >> 4;
#pragma unroll
    for (int ks = 0; ks < 2; ks++) {
        uint32_t a4[4][4], bh[8][2], t4[4];
#pragma unroll
        for (int i = 0; i < 4; i++)
            ldsm4(so + 0 * MM_MAT + (wm * 64 + i * 16 + lr) * MM_SP + ks * 32 + lc * 16, a4[i]);
#pragma unroll
        for (int jj = 0; jj < 4; jj++) {
            ldsm4(so + 2 * MM_MAT + (wn * 64 + jj * 16 + lr) * MM_SP + ks * 32 + lc * 16, t4);
            bh[2 * jj][0] = t4[0]; bh[2 * jj][1] = t4[2];
            bh[2 * jj + 1][0] = t4[1]; bh[2 * jj + 1][1] = t4[3];
        }
        // main: Ah*Bh, f32 acc
#pragma unroll
        for (int i = 0; i < 4; i++)
#pragma unroll
            for (int j = 0; j < 8; j++)
                mma16816(acc[i][j], a4[i], bh[j][0], bh[j][1]);
        if (CORR) {
#pragma unroll
            for (int i = 0; i < 4; i++)
                ldsm4(so + 1 * MM_MAT + (wm * 64 + i * 16 + lr) * MM_SP + ks * 32 + lc * 16, a4[i]);
#pragma unroll
            for (int i = 0; i < 4; i++)
#pragma unroll
                for (int j = 0; j < 8; j++)
                    mma16816h(corr[i][j], a4[i], bh[j][0], bh[j][1]);
        }
    }
}

// mode 0: rope + hi/lo (Q); 1: rope + hi (K); 2: hi (V); 3: fp32 (final out).
template<bool CORR>
__device__ void mm_body(const __half* Ah, const __half* Al, const __half* Bh,
                        int mode, float* outF, __half* outH, __half* outL) {
    extern __shared__ char smem[];
    uint32_t sb = smem_u32(smem);
    const int tid = threadIdx.x, lane = tid & 31, wid = tid >> 5;
    const int wm = wid >> 1, wn = wid & 1;
    const int m0 = blockIdx.y * 128, n0 = blockIdx.x * 128;

    const __half* A_h = Ah + (size_t)m0 * D;
    const __half* A_l = CORR ? Al + (size_t)m0 * D : (const __half*)0;
    const __half* B_h = Bh + (size_t)n0 * D;

    float acc[4][8][4];
    uint32_t corr[4][8][2];
#pragma unroll
    for (int i = 0; i < 4; i++)
#pragma unroll
        for (int j = 0; j < 8; j++) {
#pragma unroll
            for (int e = 0; e < 4; e++) acc[i][j][e] = 0.0f;
            corr[i][j][0] = 0u; corr[i][j][1] = 0u;
        }

    mm_load_stage<CORR>(sb, 0, 0, A_h, A_l, B_h);
    asm volatile("cp.async.commit_group;" ::: "memory");

#pragma unroll 1
    for (int c = 0; c < 32; c++) {
        int st = c & 1;
        if (c + 1 < 32) {
            mm_load_stage<CORR>(sb, st ^ 1, c + 1, A_h, A_l, B_h);
            asm volatile("cp.async.commit_group;" ::: "memory");
            asm volatile("cp.async.wait_group 1;" ::: "memory");
        } else {
            asm volatile("cp.async.wait_group 0;" ::: "memory");
        }
        __syncthreads();
        mm_stage_compute<CORR>(sb + st * MM_STAGE, wm, wn, lane, acc, corr);
        __syncthreads();
    }

    const int g = lane >> 2, tig = lane & 3;
#pragma unroll
    for (int i = 0; i < 4; i++)
#pragma unroll
        for (int j = 0; j < 8; j++) {
            if (CORR) {
                float2 c01 = __half22float2(*(__half2*)&corr[i][j][0]);
                float2 c23 = __half22float2(*(__half2*)&corr[i][j][1]);
                acc[i][j][0] += c01.x * INV_LO; acc[i][j][1] += c01.y * INV_LO;
                acc[i][j][2] += c23.x * INV_LO; acc[i][j][3] += c23.y * INV_LO;
            }
            const int m = m0 + wm * 64 + i * 16 + g;
            const int n = n0 + wn * 64 + j * 8 + tig * 2;
#pragma unroll
            for (int rr = 0; rr < 2; rr++) {
                const int mm = m + rr * 8;
                float e = acc[i][j][rr * 2], o = acc[i][j][rr * 2 + 1];
                if (mode <= 1) {
                    const int pidx = (n & 63) >> 1;
                    const float cv = g_cos[mm * 32 + pidx];
                    const float sv = g_sin[mm * 32 + pidx];
                    const float e2 = e * cv - o * sv;
                    const float o2 = e * sv + o * cv;
                    e = e2; o = o2;
                }
                if (mode == 3) {
                    *(float2*)(outF + (size_t)mm * D + n) = make_float2(e, o);
                } else {
                    __half he = __float2half_rn(e), ho = __float2half_rn(o);
                    *(uint32_t*)(outH + (size_t)mm * D + n) =
                        ((uint32_t)__half_as_ushort(ho) << 16) | __half_as_ushort(he);
                    if (mode == 0) {
                        float le = (e - __half2float(he)) * LO_SCALE;
                        float lo_ = (o - __half2float(ho)) * LO_SCALE;
                        *(uint32_t*)(outL + (size_t)mm * D + n) = pack_h2(le, lo_);
                    }
                }
            }
        }
}

__global__ __launch_bounds__(128, 2) void mm_qkv_kernel() {
    const int z = blockIdx.z;
    const __half* Bh = g_Whi + (size_t)z * D * D;
    if (z == 0)      mm_body<true >(g_Xhi, g_Xlo, Bh, 0, (float*)0, g_Qhi, g_Qlo);
    else if (z == 1) mm_body<false>(g_Xhi, (const __half*)0, Bh, 1, (float*)0, g_Khi, (__half*)0);
    else             mm_body<false>(g_Xhi, (const __half*)0, Bh, 2, (float*)0, g_Vhi, (__half*)0);
}

__global__ __launch_bounds__(128, 2) void mm_out_kernel(float* __restrict__ out) {
    mm_body<false>(g_Ohi, (const __half*)0, g_Whi + 3ull * D * D, 3, out, (__half*)0, (__half*)0);
}

// ---------------- HMMA flash attention --------------------------------------
// CTA = 64 q rows x 1 head, 4 warps. kv tiles of 64 (hi only), double-buffered.
// S: Qh*Kh (f32) + Ql'*Kh (f16 corr). PV: Ph*Vh only (f32).
#define AT_SP    144
#define AT_MAT   (64 * AT_SP)
#define AT_KVOFF (2 * AT_MAT)          // after Qh, Ql
#define AT_STAGE (2 * AT_MAT)          // Kh, Vh per stage
#define AT_SMEM  (AT_KVOFF + 2 * AT_STAGE)   // 55296 B

__device__ __forceinline__ void at_load64(uint32_t sdst, const __half* g) {
    int t = threadIdx.x;
#pragma unroll
    for (int i = 0; i < 4; i++) {
        int cid = t + i * 128;
        int r = cid >> 3;
        int q = cid & 7;
        cp16(sdst + r * AT_SP + q * 16, g + (size_t)r * D + q * 8);
    }
}

__global__ __launch_bounds__(128) void attn_kernel() {
    extern __shared__ char smem[];
    uint32_t sb = smem_u32(smem);
    const int tid = threadIdx.x, lane = tid & 31, w = tid >> 5;
    const int qt = (int)gridDim.x - 1 - (int)blockIdx.x;   // heavy first
    const int h = blockIdx.y;
    const int qbase = qt * 64;
    const int lr = lane & 15, lc = lane >> 4;
    const int g = lane >> 2, tig = lane & 3;

    // Q hi/lo + KV tile 0 into stage 0, one commit group
    at_load64(sb + 0 * AT_MAT, g_Qhi + (size_t)qbase * D + h * HD);
    at_load64(sb + 1 * AT_MAT, g_Qlo + (size_t)qbase * D + h * HD);
    at_load64(sb + AT_KVOFF + 0 * AT_MAT, g_Khi + (size_t)h * HD);
    at_load64(sb + AT_KVOFF + 1 * AT_MAT, g_Vhi + (size_t)h * HD);
    asm volatile("cp.async.commit_group;" ::: "memory");

    uint32_t qh[4][4], ql[4][4];
    bool qloaded = false;

    float o[8][4];
#pragma unroll
    for (int j = 0; j < 8; j++)
#pragma unroll
        for (int e = 0; e < 4; e++) o[j][e] = 0.0f;
    float m0r = -1e30f, m1r = -1e30f, l0 = 0.0f, l1 = 0.0f;

#pragma unroll 1
    for (int kt = 0; kt <= qt; kt++) {
        if (kt < qt) {
            const size_t nkoff = (size_t)((kt + 1) * 64) * D + h * HD;
            const uint32_t nb = sb + AT_KVOFF + ((kt + 1) & 1) * AT_STAGE;
            at_load64(nb + 0 * AT_MAT, g_Khi + nkoff);
            at_load64(nb + 1 * AT_MAT, g_Vhi + nkoff);
            asm volatile("cp.async.commit_group;" ::: "memory");
            asm volatile("cp.async.wait_group 1;" ::: "memory");
        } else {
            asm volatile("cp.async.wait_group 0;" ::: "memory");
        }
        __syncthreads();

        if (!qloaded) {
            qloaded = true;
#pragma unroll
            for (int ks = 0; ks < 4; ks++) {
                ldsm4(sb + 0 * AT_MAT + (w * 16 + lr) * AT_SP + ks * 32 + lc * 16, qh[ks]);
                ldsm4(sb + 1 * AT_MAT + (w * 16 + lr) * AT_SP + ks * 32 + lc * 16, ql[ks]);
            }
        }

        const uint32_t kb = sb + AT_KVOFF + (kt & 1) * AT_STAGE;
        const uint32_t sK = kb, sV = kb + AT_MAT;

        float s[8][4];
        uint32_t scorr[8][2];
#pragma unroll
        for (int j = 0; j < 8; j++) {
#pragma unroll
            for (int e = 0; e < 4; e++) s[j][e] = 0.0f;
            scorr[j][0] = 0u; scorr[j][1] = 0u;
        }

        // --- S: Qh*Kh (f32) + Ql'*Kh (f16 corr) ---
#pragma unroll
        for (int ks = 0; ks < 4; ks++) {
            uint32_t kh[4][4];
#pragma unroll
            for (int jj = 0; jj < 4; jj++)
                ldsm4(sK + (jj * 16 + lr) * AT_SP + ks * 32 + lc * 16, kh[jj]);
#pragma unroll
            for (int jj = 0; jj < 4; jj++) {
                mma16816(s[2 * jj],     qh[ks], kh[jj][0], kh[jj][2]);
                mma16816(s[2 * jj + 1], qh[ks], kh[jj][1], kh[jj][3]);
            }
#pragma unroll
            for (int jj = 0; jj < 4; jj++) {
                mma16816h(scorr[2 * jj],     ql[ks], kh[jj][0], kh[jj][2]);
                mma16816h(scorr[2 * jj + 1], ql[ks], kh[jj][1], kh[jj][3]);
            }
        }

        // --- fold corr, scale + causal mask ---
        const bool diag = (kt == qt);
#pragma unroll
        for (int j = 0; j < 8; j++) {
            float2 c01 = __half22float2(*(__half2*)&scorr[j][0]);
            float2 c23 = __half22float2(*(__half2*)&scorr[j][1]);
            s[j][0] += c01.x * INV_LO; s[j][1] += c01.y * INV_LO;
            s[j][2] += c23.x * INV_LO; s[j][3] += c23.y * INV_LO;
#pragma unroll
            for (int e = 0; e < 4; e++) {
                float v = s[j][e] * 0.125f;
                if (diag) {
                    const int kvc = kt * 64 + j * 8 + tig * 2 + (e & 1);
                    const int qr  = qbase + w * 16 + g + ((e >> 1) << 3);
                    if (kvc > qr) v = -1e30f;
                }
                s[j][e] = v;
            }
        }

        // --- online softmax ---
        float mx0 = -1e30f, mx1 = -1e30f;
#pragma unroll
        for (int j = 0; j < 8; j++) {
            mx0 = fmaxf(mx0, fmaxf(s[j][0], s[j][1]));
            mx1 = fmaxf(mx1, fmaxf(s[j][2], s[j][3]));
        }
        mx0 = fmaxf(mx0, __shfl_xor_sync(0xffffffffu, mx0, 1));
        mx0 = fmaxf(mx0, __shfl_xor_sync(0xffffffffu, mx0, 2));
        mx1 = fmaxf(mx1, __shfl_xor_sync(0xffffffffu, mx1, 1));
        mx1 = fmaxf(mx1, __shfl_xor_sync(0xffffffffu, mx1, 2));
        const float nm0 = fmaxf(m0r, mx0), nm1 = fmaxf(m1r, mx1);
        const float sc0 = __expf(m0r - nm0), sc1 = __expf(m1r - nm1);
        m0r = nm0; m1r = nm1;
        l0 *= sc0; l1 *= sc1;
#pragma unroll
        for (int j = 0; j < 8; j++) {
            o[j][0] *= sc0; o[j][1] *= sc0;
            o[j][2] *= sc1; o[j][3] *= sc1;
        }
#pragma unroll
        for (int j = 0; j < 8; j++) {
            s[j][0] = __expf(s[j][0] - nm0); s[j][1] = __expf(s[j][1] - nm0);
            s[j][2] = __expf(s[j][2] - nm1); s[j][3] = __expf(s[j][3] - nm1);
            l0 += s[j][0] + s[j][1];
            l1 += s[j][2] + s[j][3];
        }

        // --- O: Ph*Vh (f32) only ---
#pragma unroll
        for (int ks = 0; ks < 4; ks++) {
            uint32_t pa[4];
#pragma unroll
            for (int hv = 0; hv < 2; hv++) {
                pa[2 * hv]     = pack_h2(s[2 * ks + hv][0], s[2 * ks + hv][1]);
                pa[2 * hv + 1] = pack_h2(s[2 * ks + hv][2], s[2 * ks + hv][3]);
            }
            uint32_t vh[4][4];
#pragma unroll
            for (int jj = 0; jj < 4; jj++)
                ldsm4t(sV + (ks * 16 + lr) * AT_SP + jj * 32 + lc * 16, vh[jj]);
#pragma unroll
            for (int jj = 0; jj < 4; jj++) {
                mma16816(o[2 * jj],     pa, vh[jj][0], vh[jj][1]);
                mma16816(o[2 * jj + 1], pa, vh[jj][2], vh[jj][3]);
            }
        }
        __syncthreads();   // all warps done with this stage before iter kt+1 overwrites the other
    }

    // --- finalize ---
    l0 += __shfl_xor_sync(0xffffffffu, l0, 1);
    l0 += __shfl_xor_sync(0xffffffffu, l0, 2);
    l1 += __shfl_xor_sync(0xffffffffu, l1, 1);
    l1 += __shfl_xor_sync(0xffffffffu, l1, 2);
    const float i0 = 1.0f / l0, i1 = 1.0f / l1;

#pragma unroll
    for (int j = 0; j < 8; j++) {
        const int n = h * HD + j * 8 + tig * 2;
#pragma unroll
        for (int rr = 0; rr < 2; rr++) {
            const int mm = qbase + w * 16 + g + rr * 8;
            const float inv = rr ? i1 : i0;
            const float e = o[j][2 * rr] * inv;
            const float od = o[j][2 * rr + 1] * inv;
            *(uint32_t*)(g_Ohi + (size_t)mm * D + n) = pack_h2(e, od);
        }
    }
}

// ---------------------------------------------------------------------------
extern "C" void kernel_launch(void* const* d_in, const int* in_sizes, int n_in,
                              void* d_out, int out_size) {
    (void)in_sizes; (void)n_in; (void)out_size;
    const float* x   = (const float*)d_in[0];
    const int*   pos = (const int*)  d_in[1];
    const float* Wq  = (const float*)d_in[2];
    const float* Wk  = (const float*)d_in[3];
    const float* Wv  = (const float*)d_in[4];
    const float* Wo  = (const float*)d_in[5];
    float* out = (float*)d_out;

    cudaFuncSetAttribute(mm_qkv_kernel, cudaFuncAttributeMaxDynamicSharedMemorySize, MM_SMEM);
    cudaFuncSetAttribute(mm_out_kernel, cudaFuncAttributeMaxDynamicSharedMemorySize, MM_SMEM);
    cudaFuncSetAttribute(attn_kernel, cudaFuncAttributeMaxDynamicSharedMemorySize, AT_SMEM);

    split_x_kernel<<<(S * D) / 256, 256>>>(x);
    split_w_kernel<<<dim3((D * D) / 256, 1, 4), 256>>>(Wq, Wk, Wv, Wo);
    rope_table_kernel<<<S, 32>>>(pos);

    mm_qkv_kernel<<<dim3(D / 128, S / 128, 3), 128, MM_SMEM>>>();
    attn_kernel<<<dim3(S / 64, H), 128, AT_SMEM>>>();
    mm_out_kernel<<<dim3(D / 128, S / 128, 1), 128, MM_SMEM>>>(out);
}

// round 12
// speedup vs baseline: 2.3614x; 1.1667x over previous
#include <cuda_runtime.h>
#include <cuda_fp16.h>
#include <cstdint>
#include <math.h>

#define S 4096
#define D 1024
#define H 16
#define HD 64

// ---------------- device scratch -------------------------------------------
__device__ __half g_Xhi[(size_t)S * D];
__device__ __half g_Whi[4 * (size_t)D * D];
__device__ __half g_Qhi[(size_t)S * D];
__device__ __half g_Khi[(size_t)S * D];
__device__ __half g_Vhi[(size_t)S * D];
__device__ __half g_Ohi[(size_t)S * D];
__device__ float g_cos[S * 32], g_sin[S * 32];

// ---------------- helpers ---------------------------------------------------
__device__ __forceinline__ uint32_t smem_u32(const void* p) {
    uint32_t a;
    asm("{ .reg .u64 t; cvta.to.shared.u64 t, %1; cvt.u32.u64 %0, t; }"
        : "=r"(a) : "l"(p));
    return a;
}

__device__ __forceinline__ void cp16(uint32_t saddr, const void* g) {
    asm volatile("cp.async.cg.shared.global [%0], [%1], 16;" :: "r"(saddr), "l"(g));
}

__device__ __forceinline__ void ldsm4(uint32_t a, uint32_t r[4]) {
    asm volatile("ldmatrix.sync.aligned.m8n8.x4.shared.b16 {%0,%1,%2,%3}, [%4];"
                 : "=r"(r[0]), "=r"(r[1]), "=r"(r[2]), "=r"(r[3]) : "r"(a));
}

__device__ __forceinline__ void ldsm4t(uint32_t a, uint32_t r[4]) {
    asm volatile("ldmatrix.sync.aligned.m8n8.x4.trans.shared.b16 {%0,%1,%2,%3}, [%4];"
                 : "=r"(r[0]), "=r"(r[1]), "=r"(r[2]), "=r"(r[3]) : "r"(a));
}

// f32-accumulate fp16 MMA
__device__ __forceinline__ void mma16816(float c[4], const uint32_t a[4],
                                         uint32_t b0, uint32_t b1) {
    asm("mma.sync.aligned.m16n8k16.row.col.f32.f16.f16.f32 "
        "{%0,%1,%2,%3}, {%4,%5,%6,%7}, {%8,%9}, {%0,%1,%2,%3};"
        : "+f"(c[0]), "+f"(c[1]), "+f"(c[2]), "+f"(c[3])
        : "r"(a[0]), "r"(a[1]), "r"(a[2]), "r"(a[3]), "r"(b0), "r"(b1));
}

__device__ __forceinline__ uint32_t pack_h2(float a, float b) {
    __half2 h = __floats2half2_rn(a, b);
    return *(uint32_t*)&h;
}

// ---------------- conversion / rope-table kernels ---------------------------
__global__ void split_x_kernel(const float* __restrict__ x) {
    size_t i = (size_t)blockIdx.x * 256 + threadIdx.x;
    g_Xhi[i] = __float2half_rn(x[i]);
}

__global__ void split_w_kernel(const float* __restrict__ Wq, const float* __restrict__ Wk,
                               const float* __restrict__ Wv, const float* __restrict__ Wo) {
    int z = blockIdx.z;
    const float* W = (z == 0) ? Wq : (z == 1) ? Wk : (z == 2) ? Wv : Wo;
    size_t i = (size_t)blockIdx.x * 256 + threadIdx.x;
    g_Whi[(size_t)z * D * D + i] = __float2half_rn(W[i]);
}

__global__ void rope_table_kernel(const int* __restrict__ pos) {
    int m = blockIdx.x;
    int i = threadIdx.x;  // pair index 0..31
    double f = pow(10000.0, -(double)(2 * i) / 64.0);
    float ang = (float)pos[m] * (float)f;
    float sv, cv;
    sincosf(ang, &sv, &cv);
    g_cos[m * 32 + i] = cv;
    g_sin[m * 32 + i] = sv;
}

// ---------------- fp16 HMMA GEMM:  Y = A @ B^T --------------------------------
// CTA 128x128, 4 warps (2x2), each warp 64x64. k-chunk 32, double-buffered.
#define MM_SP    80
#define MM_MAT   (128 * MM_SP)
#define MM_STAGE (2 * MM_MAT)      // Ah, Bh
#define MM_SMEM  (2 * MM_STAGE)    // 40960 B

__device__ __forceinline__ void mm_load_stage(uint32_t sb, int st, int c,
                                              const __half* A_h, const __half* B_h) {
    const __half* srcs[2] = {A_h, B_h};
    int t = threadIdx.x;
#pragma unroll
    for (int i = 0; i < 8; i++) {
        int cid = t + i * 128;
        int mi = cid >> 9;                 // 0 -> Ah, 1 -> Bh
        int r  = (cid >> 2) & 127;
        int q  = cid & 3;
        cp16(sb + st * MM_STAGE + mi * MM_MAT + r * MM_SP + q * 16,
             srcs[mi] + (size_t)r * D + c * 32 + q * 8);
    }
}

__device__ __forceinline__ void mm_stage_compute(uint32_t so, int wm, int wn, int lane,
                                                 float acc[4][8][4]) {
    const int lr = lane & 15, lc = lane >> 4;
#pragma unroll
    for (int ks = 0; ks < 2; ks++) {
        uint32_t a4[4][4], bh[8][2], t4[4];
#pragma unroll
        for (int i = 0; i < 4; i++)
            ldsm4(so + 0 * MM_MAT + (wm * 64 + i * 16 + lr) * MM_SP + ks * 32 + lc * 16, a4[i]);
#pragma unroll
        for (int jj = 0; jj < 4; jj++) {
            ldsm4(so + 1 * MM_MAT + (wn * 64 + jj * 16 + lr) * MM_SP + ks * 32 + lc * 16, t4);
            bh[2 * jj][0] = t4[0]; bh[2 * jj][1] = t4[2];
            bh[2 * jj + 1][0] = t4[1]; bh[2 * jj + 1][1] = t4[3];
        }
#pragma unroll
        for (int i = 0; i < 4; i++)
#pragma unroll
            for (int j = 0; j < 8; j++)
                mma16816(acc[i][j], a4[i], bh[j][0], bh[j][1]);
    }
}

// mode 1: rope + fp16 out (Q/K); 2: fp16 out (V); 3: fp32 out (final).
__device__ void mm_body(const __half* Ah, const __half* Bh,
                        int mode, float* outF, __half* outH) {
    extern __shared__ char smem[];
    uint32_t sb = smem_u32(smem);
    const int tid = threadIdx.x, lane = tid & 31, wid = tid >> 5;
    const int wm = wid >> 1, wn = wid & 1;
    const int m0 = blockIdx.y * 128, n0 = blockIdx.x * 128;

    const __half* A_h = Ah + (size_t)m0 * D;
    const __half* B_h = Bh + (size_t)n0 * D;

    float acc[4][8][4];
#pragma unroll
    for (int i = 0; i < 4; i++)
#pragma unroll
        for (int j = 0; j < 8; j++)
#pragma unroll
            for (int e = 0; e < 4; e++) acc[i][j][e] = 0.0f;

    mm_load_stage(sb, 0, 0, A_h, B_h);
    asm volatile("cp.async.commit_group;" ::: "memory");

#pragma unroll 1
    for (int c = 0; c < 32; c++) {
        int st = c & 1;
        if (c + 1 < 32) {
            mm_load_stage(sb, st ^ 1, c + 1, A_h, B_h);
            asm volatile("cp.async.commit_group;" ::: "memory");
            asm volatile("cp.async.wait_group 1;" ::: "memory");
        } else {
            asm volatile("cp.async.wait_group 0;" ::: "memory");
        }
        __syncthreads();
        mm_stage_compute(sb + st * MM_STAGE, wm, wn, lane, acc);
        __syncthreads();
    }

    const int g = lane >> 2, tig = lane & 3;
#pragma unroll
    for (int i = 0; i < 4; i++)
#pragma unroll
        for (int j = 0; j < 8; j++) {
            const int m = m0 + wm * 64 + i * 16 + g;
            const int n = n0 + wn * 64 + j * 8 + tig * 2;
#pragma unroll
            for (int rr = 0; rr < 2; rr++) {
                const int mm = m + rr * 8;
                float e = acc[i][j][rr * 2], o = acc[i][j][rr * 2 + 1];
                if (mode == 1) {
                    const int pidx = (n & 63) >> 1;
                    const float cv = g_cos[mm * 32 + pidx];
                    const float sv = g_sin[mm * 32 + pidx];
                    const float e2 = e * cv - o * sv;
                    const float o2 = e * sv + o * cv;
                    e = e2; o = o2;
                }
                if (mode == 3) {
                    *(float2*)(outF + (size_t)mm * D + n) = make_float2(e, o);
                } else {
                    *(uint32_t*)(outH + (size_t)mm * D + n) = pack_h2(e, o);
                }
            }
        }
}

__global__ __launch_bounds__(128, 2) void mm_qkv_kernel() {
    const int z = blockIdx.z;
    const __half* Bh = g_Whi + (size_t)z * D * D;
    if (z == 0)      mm_body(g_Xhi, Bh, 1, (float*)0, g_Qhi);
    else if (z == 1) mm_body(g_Xhi, Bh, 1, (float*)0, g_Khi);
    else             mm_body(g_Xhi, Bh, 2, (float*)0, g_Vhi);
}

__global__ __launch_bounds__(128, 2) void mm_out_kernel(float* __restrict__ out) {
    mm_body(g_Ohi, g_Whi + 3ull * D * D, 3, out, (__half*)0);
}

// ---------------- HMMA flash attention --------------------------------------
// CTA = 64 q rows x 1 head, 4 warps. kv tiles of 64, double-buffered.
// S: Qh*Kh (f32). PV: Ph*Vh (f32). Plain fp16 operands throughout.
#define AT_SP    144
#define AT_MAT   (64 * AT_SP)
#define AT_KVOFF (1 * AT_MAT)          // after Qh
#define AT_STAGE (2 * AT_MAT)          // Kh, Vh per stage
#define AT_SMEM  (AT_KVOFF + 2 * AT_STAGE)   // 46080 B

__device__ __forceinline__ void at_load64(uint32_t sdst, const __half* g) {
    int t = threadIdx.x;
#pragma unroll
    for (int i = 0; i < 4; i++) {
        int cid = t + i * 128;
        int r = cid >> 3;
        int q = cid & 7;
        cp16(sdst + r * AT_SP + q * 16, g + (size_t)r * D + q * 8);
    }
}

__global__ __launch_bounds__(128) void attn_kernel() {
    extern __shared__ char smem[];
    uint32_t sb = smem_u32(smem);
    const int tid = threadIdx.x, lane = tid & 31, w = tid >> 5;
    const int qt = (int)gridDim.x - 1 - (int)blockIdx.x;   // heavy first
    const int h = blockIdx.y;
    const int qbase = qt * 64;
    const int lr = lane & 15, lc = lane >> 4;
    const int g = lane >> 2, tig = lane & 3;

    // Q + KV tile 0 into stage 0
    at_load64(sb, g_Qhi + (size_t)qbase * D + h * HD);
    at_load64(sb + AT_KVOFF + 0 * AT_MAT, g_Khi + (size_t)h * HD);
    at_load64(sb + AT_KVOFF + 1 * AT_MAT, g_Vhi + (size_t)h * HD);
    asm volatile("cp.async.commit_group;" ::: "memory");

    uint32_t qh[4][4];
    bool qloaded = false;

    float o[8][4];
#pragma unroll
    for (int j = 0; j < 8; j++)
#pragma unroll
        for (int e = 0; e < 4; e++) o[j][e] = 0.0f;
    float m0r = -1e30f, m1r = -1e30f, l0 = 0.0f, l1 = 0.0f;

#pragma unroll 1
    for (int kt = 0; kt <= qt; kt++) {
        if (kt < qt) {
            const size_t nkoff = (size_t)((kt + 1) * 64) * D + h * HD;
            const uint32_t nb = sb + AT_KVOFF + ((kt + 1) & 1) * AT_STAGE;
            at_load64(nb + 0 * AT_MAT, g_Khi + nkoff);
            at_load64(nb + 1 * AT_MAT, g_Vhi + nkoff);
            asm volatile("cp.async.commit_group;" ::: "memory");
            asm volatile("cp.async.wait_group 1;" ::: "memory");
        } else {
            asm volatile("cp.async.wait_group 0;" ::: "memory");
        }
        __syncthreads();

        if (!qloaded) {
            qloaded = true;
#pragma unroll
            for (int ks = 0; ks < 4; ks++)
                ldsm4(sb + (w * 16 + lr) * AT_SP + ks * 32 + lc * 16, qh[ks]);
        }

        const uint32_t kb = sb + AT_KVOFF + (kt & 1) * AT_STAGE;
        const uint32_t sK = kb, sV = kb + AT_MAT;

        float s[8][4];
#pragma unroll
        for (int j = 0; j < 8; j++)
#pragma unroll
            for (int e = 0; e < 4; e++) s[j][e] = 0.0f;

        // --- S = Qh*Kh^T (f32) ---
#pragma unroll
        for (int ks = 0; ks < 4; ks++) {
            uint32_t kh[4][4];
#pragma unroll
            for (int jj = 0; jj < 4; jj++)
                ldsm4(sK + (jj * 16 + lr) * AT_SP + ks * 32 + lc * 16, kh[jj]);
#pragma unroll
            for (int jj = 0; jj < 4; jj++) {
                mma16816(s[2 * jj],     qh[ks], kh[jj][0], kh[jj][2]);
                mma16816(s[2 * jj + 1], qh[ks], kh[jj][1], kh[jj][3]);
            }
        }

        // --- scale + causal mask ---
        const bool diag = (kt == qt);
#pragma unroll
        for (int j = 0; j < 8; j++)
#pragma unroll
            for (int e = 0; e < 4; e++) {
                float v = s[j][e] * 0.125f;
                if (diag) {
                    const int kvc = kt * 64 + j * 8 + tig * 2 + (e & 1);
                    const int qr  = qbase + w * 16 + g + ((e >> 1) << 3);
                    if (kvc > qr) v = -1e30f;
                }
                s[j][e] = v;
            }

        // --- online softmax ---
        float mx0 = -1e30f, mx1 = -1e30f;
#pragma unroll
        for (int j = 0; j < 8; j++) {
            mx0 = fmaxf(mx0, fmaxf(s[j][0], s[j][1]));
            mx1 = fmaxf(mx1, fmaxf(s[j][2], s[j][3]));
        }
        mx0 = fmaxf(mx0, __shfl_xor_sync(0xffffffffu, mx0, 1));
        mx0 = fmaxf(mx0, __shfl_xor_sync(0xffffffffu, mx0, 2));
        mx1 = fmaxf(mx1, __shfl_xor_sync(0xffffffffu, mx1, 1));
        mx1 = fmaxf(mx1, __shfl_xor_sync(0xffffffffu, mx1, 2));
        const float nm0 = fmaxf(m0r, mx0), nm1 = fmaxf(m1r, mx1);
        const float sc0 = __expf(m0r - nm0), sc1 = __expf(m1r - nm1);
        m0r = nm0; m1r = nm1;
        l0 *= sc0; l1 *= sc1;
#pragma unroll
        for (int j = 0; j < 8; j++) {
            o[j][0] *= sc0; o[j][1] *= sc0;
            o[j][2] *= sc1; o[j][3] *= sc1;
        }
#pragma unroll
        for (int j = 0; j < 8; j++) {
            s[j][0] = __expf(s[j][0] - nm0); s[j][1] = __expf(s[j][1] - nm0);
            s[j][2] = __expf(s[j][2] - nm1); s[j][3] = __expf(s[j][3] - nm1);
            l0 += s[j][0] + s[j][1];
            l1 += s[j][2] + s[j][3];
        }

        // --- O += Ph*Vh (f32) ---
#pragma unroll
        for (int ks = 0; ks < 4; ks++) {
            uint32_t pa[4];
#pragma unroll
            for (int hv = 0; hv < 2; hv++) {
                pa[2 * hv]     = pack_h2(s[2 * ks + hv][0], s[2 * ks + hv][1]);
                pa[2 * hv + 1] = pack_h2(s[2 * ks + hv][2], s[2 * ks + hv][3]);
            }
            uint32_t vh[4][4];
#pragma unroll
            for (int jj = 0; jj < 4; jj++)
                ldsm4t(sV + (ks * 16 + lr) * AT_SP + jj * 32 + lc * 16, vh[jj]);
#pragma unroll
            for (int jj = 0; jj < 4; jj++) {
                mma16816(o[2 * jj],     pa, vh[jj][0], vh[jj][1]);
                mma16816(o[2 * jj + 1], pa, vh[jj][2], vh[jj][3]);
            }
        }
        __syncthreads();   // all warps done with this stage before it is overwritten
    }

    // --- finalize ---
    l0 += __shfl_xor_sync(0xffffffffu, l0, 1);
    l0 += __shfl_xor_sync(0xffffffffu, l0, 2);
    l1 += __shfl_xor_sync(0xffffffffu, l1, 1);
    l1 += __shfl_xor_sync(0xffffffffu, l1, 2);
    const float i0 = 1.0f / l0, i1 = 1.0f / l1;

#pragma unroll
    for (int j = 0; j < 8; j++) {
        const int n = h * HD + j * 8 + tig * 2;
#pragma unroll
        for (int rr = 0; rr < 2; rr++) {
            const int mm = qbase + w * 16 + g + rr * 8;
            const float inv = rr ? i1 : i0;
            *(uint32_t*)(g_Ohi + (size_t)mm * D + n) =
                pack_h2(o[j][2 * rr] * inv, o[j][2 * rr + 1] * inv);
        }
    }
}

// ---------------------------------------------------------------------------
extern "C" void kernel_launch(void* const* d_in, const int* in_sizes, int n_in,
                              void* d_out, int out_size) {
    (void)in_sizes; (void)n_in; (void)out_size;
    const float* x   = (const float*)d_in[0];
    const int*   pos = (const int*)  d_in[1];
    const float* Wq  = (const float*)d_in[2];
    const float* Wk  = (const float*)d_in[3];
    const float* Wv  = (const float*)d_in[4];
    const float* Wo  = (const float*)d_in[5];
    float* out = (float*)d_out;

    cudaFuncSetAttribute(mm_qkv_kernel, cudaFuncAttributeMaxDynamicSharedMemorySize, MM_SMEM);
    cudaFuncSetAttribute(mm_out_kernel, cudaFuncAttributeMaxDynamicSharedMemorySize, MM_SMEM);
    cudaFuncSetAttribute(attn_kernel, cudaFuncAttributeMaxDynamicSharedMemorySize, AT_SMEM);

    split_x_kernel<<<(S * D) / 256, 256>>>(x);
    split_w_kernel<<<dim3((D * D) / 256, 1, 4), 256>>>(Wq, Wk, Wv, Wo);
    rope_table_kernel<<<S, 32>>>(pos);

    mm_qkv_kernel<<<dim3(D / 128, S / 128, 3), 128, MM_SMEM>>>();
    attn_kernel<<<dim3(S / 64, H), 128, AT_SMEM>>>();
    mm_out_kernel<<<dim3(D / 128, S / 128, 1), 128, MM_SMEM>>>(out);
}